// round 3
// baseline (speedup 1.0000x reference)
#include <cuda_runtime.h>
#include <math.h>

#define CB   2
#define CS   4096
#define CD   1024
#define CH   16
#define CHD  64
#define CNB  64      /* S / BLOCK */
#define CW   8
#define CM   (CB*CS) /* 8192 rows */

// ---------------- scratch (device globals: no allocations allowed) ----------
__device__ float g_q[(size_t)CB*CH*CS*CHD];     // (b,h,s,hd)
__device__ float g_k[(size_t)CB*CH*CS*CHD];
__device__ float g_v[(size_t)CB*CH*CS*CHD];
__device__ float g_attn[(size_t)CB*CS*CD];      // (b,s,h*64+hd) row-major
__device__ float g_cos[CS*32];
__device__ float g_sin[CS*32];

// ---------------- RoPE tables (double precision -> fp32 table) --------------
__global__ void rope_table_kernel() {
    int idx = blockIdx.x * blockDim.x + threadIdx.x;
    if (idx >= CS*32) return;
    int p = idx >> 5;
    int j = idx & 31;
    double expo = (double)(2*j) / 64.0;
    double freq = exp(-expo * log(10000.0));
    double ang  = (double)p * freq;
    g_cos[idx] = (float)cos(ang);
    g_sin[idx] = (float)sin(ang);
}

// ---------------- RoPE apply (in-place on g_q, g_k) -------------------------
__global__ void rope_apply_kernel(const int* __restrict__ posids) {
    int idx = blockIdx.x * blockDim.x + threadIdx.x;   // B*H*S*32 threads
    int j  = idx & 31;
    int s  = (idx >> 5) & (CS - 1);
    int bh = idx >> 17;
    int b  = bh >> 4;
    int p  = posids[b*CS + s];
    float c  = g_cos[p*32 + j];
    float sn = g_sin[p*32 + j];
    size_t base = ((size_t)bh*CS + (size_t)s)*CHD + j;
    float q1 = g_q[base], q2 = g_q[base+32];
    g_q[base]    = q1*c - q2*sn;
    g_q[base+32] = q2*c + q1*sn;
    float k1 = g_k[base], k2 = g_k[base+32];
    g_k[base]    = k1*c - k2*sn;
    g_k[base+32] = k2*c + k1*sn;
}

// ---------------- tiled fp32 GEMM: C[8192x1024] = A[8192x1024] @ W[1024x1024]
// mode 0/1/2 : store transposed into g_q/g_k/g_v as (b,h,s,hd)
// mode 3     : A = g_attn, store row-major into outF
__global__ __launch_bounds__(256) void gemm64(const float* __restrict__ Ain,
                                              const float* __restrict__ Wm,
                                              float* __restrict__ outF,
                                              int mode) {
    const float* A = (mode == 3) ? (const float*)g_attn : Ain;

    __shared__ float As[64][20];   // [m][k], pad 16->20
    __shared__ float Bs[16][64];   // [k][n]

    const int tid = threadIdx.x;
    const int ty = tid >> 4;       // 0..15 -> rows ty*4..+3
    const int tx = tid & 15;       // 0..15 -> cols tx*4..+3
    const int m0 = blockIdx.x * 64;
    const int n0 = blockIdx.y * 64;

    const int a_row = tid >> 2;          // 0..63
    const int a_col = (tid & 3) << 2;    // 0,4,8,12
    const int b_row = tid >> 4;          // 0..15
    const int b_col = (tid & 15) << 2;

    float acc[4][4];
#pragma unroll
    for (int i = 0; i < 4; i++)
#pragma unroll
        for (int j = 0; j < 4; j++) acc[i][j] = 0.f;

    const float* Aptr = A  + (size_t)(m0 + a_row)*CD + a_col;
    const float* Wptr = Wm + (size_t)b_row*CD + n0 + b_col;

    for (int k0 = 0; k0 < CD; k0 += 16) {
        float4 av = *(const float4*)(Aptr + k0);
        float4 bv = *(const float4*)(Wptr + (size_t)k0*CD);
        __syncthreads();
        *(float4*)&As[a_row][a_col] = av;
        *(float4*)&Bs[b_row][b_col] = bv;
        __syncthreads();
#pragma unroll
        for (int k = 0; k < 16; k++) {
            float ra0 = As[ty*4+0][k];
            float ra1 = As[ty*4+1][k];
            float ra2 = As[ty*4+2][k];
            float ra3 = As[ty*4+3][k];
            float4 rb = *(float4*)&Bs[k][tx*4];
            acc[0][0] = fmaf(ra0, rb.x, acc[0][0]);
            acc[0][1] = fmaf(ra0, rb.y, acc[0][1]);
            acc[0][2] = fmaf(ra0, rb.z, acc[0][2]);
            acc[0][3] = fmaf(ra0, rb.w, acc[0][3]);
            acc[1][0] = fmaf(ra1, rb.x, acc[1][0]);
            acc[1][1] = fmaf(ra1, rb.y, acc[1][1]);
            acc[1][2] = fmaf(ra1, rb.z, acc[1][2]);
            acc[1][3] = fmaf(ra1, rb.w, acc[1][3]);
            acc[2][0] = fmaf(ra2, rb.x, acc[2][0]);
            acc[2][1] = fmaf(ra2, rb.y, acc[2][1]);
            acc[2][2] = fmaf(ra2, rb.z, acc[2][2]);
            acc[2][3] = fmaf(ra2, rb.w, acc[2][3]);
            acc[3][0] = fmaf(ra3, rb.x, acc[3][0]);
            acc[3][1] = fmaf(ra3, rb.y, acc[3][1]);
            acc[3][2] = fmaf(ra3, rb.z, acc[3][2]);
            acc[3][3] = fmaf(ra3, rb.w, acc[3][3]);
        }
    }

    if (mode == 3) {
#pragma unroll
        for (int i = 0; i < 4; i++) {
            size_t off = (size_t)(m0 + ty*4 + i)*CD + n0 + tx*4;
            float4 o = make_float4(acc[i][0], acc[i][1], acc[i][2], acc[i][3]);
            *(float4*)(outF + off) = o;
        }
    } else {
        float* dst = (mode == 0) ? g_q : (mode == 1) ? g_k : g_v;
#pragma unroll
        for (int i = 0; i < 4; i++) {
            int m = m0 + ty*4 + i;
            int b = m >> 12;            // /4096
            int s = m & (CS-1);
#pragma unroll
            for (int j = 0; j < 4; j++) {
                int nn = n0 + tx*4 + j;
                int h  = nn >> 6;
                int hd = nn & 63;
                dst[(((size_t)(b*CH + h))*CS + s)*CHD + hd] = acc[i][j];
            }
        }
    }
}

// ---------------- block-sparse flash attention -------------------------------
#define PADA 65
#define PADV 68
#define ATTN_SMEM_BYTES ((64*PADA*3 + 64*PADV) * 4)   /* 67328 B */

__global__ __launch_bounds__(128) void attn_kernel() {
    extern __shared__ float sm[];
    float* qs = sm;                 // [64][65]
    float* ks = qs + 64*PADA;       // [64][65]
    float* vs = ks + 64*PADA;       // [64][68]
    float* ps = vs + 64*PADV;       // [64][65]

    const int n   = blockIdx.x;     // query block
    const int bh  = blockIdx.y;     // b*H + h
    const int tid = threadIdx.x;
    const int ty  = tid >> 3;       // 0..15  -> queries ty*4..+3
    const int tx  = tid & 7;        // 0..7   -> keys jj*8+tx, hd cols tx*8..+7
    const int q0  = ty*4;

    // load Q tile
    const float* qsrc = g_q + ((size_t)bh*CS + (size_t)n*64)*CHD;
#pragma unroll
    for (int r = 0; r < 8; r++) {
        int idx = tid + 128*r;
        int row = idx >> 4;
        int col = (idx & 15) << 2;
        float4 v = *(const float4*)(qsrc + row*CHD + col);
        float* d = qs + row*PADA + col;
        d[0]=v.x; d[1]=v.y; d[2]=v.z; d[3]=v.w;
    }

    float m_i[4], l_i[4], acc[4][8];
#pragma unroll
    for (int i = 0; i < 4; i++) {
        m_i[i] = -1e30f; l_i[i] = 0.f;
#pragma unroll
        for (int c = 0; c < 8; c++) acc[i][c] = 0.f;
    }

    for (int w = 0; w < CW; w++) {
        int kb = n - (CW-1) + w;
        if (kb < 0) continue;                 // uniform across block
        __syncthreads();                      // prev PV done before overwrite

        const float* ksrc = g_k + ((size_t)bh*CS + (size_t)kb*64)*CHD;
        const float* vsrc = g_v + ((size_t)bh*CS + (size_t)kb*64)*CHD;
#pragma unroll
        for (int r = 0; r < 8; r++) {
            int idx = tid + 128*r;
            int row = idx >> 4;
            int col = (idx & 15) << 2;
            float4 kv = *(const float4*)(ksrc + row*CHD + col);
            float* kd = ks + row*PADA + col;
            kd[0]=kv.x; kd[1]=kv.y; kd[2]=kv.z; kd[3]=kv.w;
            float4 vv = *(const float4*)(vsrc + row*CHD + col);
            *(float4*)(vs + row*PADV + col) = vv;
        }
        __syncthreads();

        // scores: 4 queries x 8 keys (key index jj*8+tx)
        float sc[4][8];
#pragma unroll
        for (int i = 0; i < 4; i++)
#pragma unroll
            for (int jj = 0; jj < 8; jj++) sc[i][jj] = 0.f;

#pragma unroll 4
        for (int d = 0; d < 64; d++) {
            float rq[4];
#pragma unroll
            for (int i = 0; i < 4; i++) rq[i] = qs[(q0+i)*PADA + d];
            float rk[8];
#pragma unroll
            for (int jj = 0; jj < 8; jj++) rk[jj] = ks[(jj*8+tx)*PADA + d];
#pragma unroll
            for (int i = 0; i < 4; i++)
#pragma unroll
                for (int jj = 0; jj < 8; jj++)
                    sc[i][jj] = fmaf(rq[i], rk[jj], sc[i][jj]);
        }

        const bool diag = (kb == n);
#pragma unroll
        for (int i = 0; i < 4; i++) {
            int qi = q0 + i;
#pragma unroll
            for (int jj = 0; jj < 8; jj++) {
                float v = sc[i][jj] * 0.125f;
                if (diag && (jj*8 + tx) > qi) v = -1e30f;
                sc[i][jj] = v;
            }
        }

        // online softmax (state replicated across the 8 tx lanes)
#pragma unroll
        for (int i = 0; i < 4; i++) {
            float mb = sc[i][0];
#pragma unroll
            for (int jj = 1; jj < 8; jj++) mb = fmaxf(mb, sc[i][jj]);
#pragma unroll
            for (int o = 1; o < 8; o <<= 1)
                mb = fmaxf(mb, __shfl_xor_sync(0xffffffffu, mb, o));
            float mn   = fmaxf(m_i[i], mb);
            float corr = __expf(m_i[i] - mn);
            float rs = 0.f;
#pragma unroll
            for (int jj = 0; jj < 8; jj++) {
                float p = __expf(sc[i][jj] - mn);
                sc[i][jj] = p;
                rs += p;
            }
#pragma unroll
            for (int o = 1; o < 8; o <<= 1)
                rs += __shfl_xor_sync(0xffffffffu, rs, o);
            l_i[i] = l_i[i]*corr + rs;
            m_i[i] = mn;
#pragma unroll
            for (int c = 0; c < 8; c++) acc[i][c] *= corr;
#pragma unroll
            for (int jj = 0; jj < 8; jj++)
                ps[(q0+i)*PADA + jj*8 + tx] = sc[i][jj];
        }
        __syncthreads();

        // PV: acc[q][hd] += sum_j P[q][j] * V[j][hd]
#pragma unroll 2
        for (int j = 0; j < 64; j++) {
            float rp[4];
#pragma unroll
            for (int i = 0; i < 4; i++) rp[i] = ps[(q0+i)*PADA + j];
            float4 v0 = *(float4*)(vs + j*PADV + tx*8);
            float4 v1 = *(float4*)(vs + j*PADV + tx*8 + 4);
#pragma unroll
            for (int i = 0; i < 4; i++) {
                acc[i][0] = fmaf(rp[i], v0.x, acc[i][0]);
                acc[i][1] = fmaf(rp[i], v0.y, acc[i][1]);
                acc[i][2] = fmaf(rp[i], v0.z, acc[i][2]);
                acc[i][3] = fmaf(rp[i], v0.w, acc[i][3]);
                acc[i][4] = fmaf(rp[i], v1.x, acc[i][4]);
                acc[i][5] = fmaf(rp[i], v1.y, acc[i][5]);
                acc[i][6] = fmaf(rp[i], v1.z, acc[i][6]);
                acc[i][7] = fmaf(rp[i], v1.w, acc[i][7]);
            }
        }
    }

    // epilogue: write (b, s, h*64+hd) row-major into g_attn
    const int b = bh >> 4;
    const int h = bh & 15;
#pragma unroll
    for (int i = 0; i < 4; i++) {
        float inv = 1.0f / l_i[i];
        int srow  = n*64 + q0 + i;
        float* o = g_attn + ((size_t)b*CS + srow)*CD + h*CHD + tx*8;
        float4 o0 = make_float4(acc[i][0]*inv, acc[i][1]*inv, acc[i][2]*inv, acc[i][3]*inv);
        float4 o1 = make_float4(acc[i][4]*inv, acc[i][5]*inv, acc[i][6]*inv, acc[i][7]*inv);
        *(float4*)o     = o0;
        *(float4*)(o+4) = o1;
    }
}

// ---------------- launch -----------------------------------------------------
extern "C" void kernel_launch(void* const* d_in, const int* in_sizes, int n_in,
                              void* d_out, int out_size) {
    const float* hidden = (const float*)d_in[0];
    const int*   posids = (const int*)d_in[1];
    const float* wq = (const float*)d_in[2];
    const float* wk = (const float*)d_in[3];
    const float* wv = (const float*)d_in[4];
    const float* wo = (const float*)d_in[5];
    float* out = (float*)d_out;

    dim3 ggrid(CM/64, CD/64);   // (128, 16)

    gemm64<<<ggrid, 256>>>(hidden, wq, nullptr, 0);
    gemm64<<<ggrid, 256>>>(hidden, wk, nullptr, 1);
    gemm64<<<ggrid, 256>>>(hidden, wv, nullptr, 2);

    rope_table_kernel<<<(CS*32 + 255)/256, 256>>>();
    rope_apply_kernel<<<(CB*CH*CS*32)/256, 256>>>(posids);

    cudaFuncSetAttribute(attn_kernel,
                         cudaFuncAttributeMaxDynamicSharedMemorySize,
                         ATTN_SMEM_BYTES);
    attn_kernel<<<dim3(CNB, CB*CH), 128, ATTN_SMEM_BYTES>>>();

    gemm64<<<ggrid, 256>>>(nullptr, wo, out, 3);
}

// round 10
// speedup vs baseline: 1.9310x; 1.9310x over previous
#include <cuda_runtime.h>
#include <cuda_bf16.h>
#include <cstdint>
#include <math.h>

#define CB   2
#define CS   4096
#define CD   1024
#define CH   16
#define CHD  64
#define CNB  64
#define CW   8
#define CM   (CB*CS)

// ---------------- scratch (device globals) ----------------------------------
__device__ float g_q[(size_t)CB*CH*CS*CHD];
__device__ float g_k[(size_t)CB*CH*CS*CHD];
__device__ float g_v[(size_t)CB*CH*CS*CHD];
__device__ float g_attn[(size_t)CB*CS*CD];
__device__ float g_cos[CS*32];
__device__ float g_sin[CS*32];
__device__ __align__(256) __nv_bfloat16 g_Ah[(size_t)CM*CD];
__device__ __align__(256) __nv_bfloat16 g_Al[(size_t)CM*CD];
__device__ __align__(256) __nv_bfloat16 g_Wh[(size_t)4*CD*CD];   // [n][k] transposed
__device__ __align__(256) __nv_bfloat16 g_Wl[(size_t)4*CD*CD];

// ---------------- helpers ----------------------------------------------------
__device__ __forceinline__ uint32_t smem_u32(const void* p) {
    uint32_t a;
    asm("{ .reg .u64 t; cvta.to.shared.u64 t, %1; cvt.u32.u64 %0, t; }" : "=r"(a) : "l"(p));
    return a;
}
#define SWZ(o) ((o) ^ (((o) >> 3) & 0x70))

#define CP16(d, s) \
    asm volatile("cp.async.cg.shared.global [%0], [%1], 16;" :: "r"((uint32_t)(d)), "l"(s) : "memory")

__device__ __forceinline__ void ldsm4(uint32_t* r, uint32_t addr) {
    asm volatile("ldmatrix.sync.aligned.m8n8.x4.shared.b16 {%0,%1,%2,%3}, [%4];"
        : "=r"(r[0]), "=r"(r[1]), "=r"(r[2]), "=r"(r[3]) : "r"(addr));
}

__device__ __forceinline__ void mma_bf16(float* c, const uint32_t* a, uint32_t b0, uint32_t b1) {
    asm volatile("mma.sync.aligned.m16n8k16.row.col.f32.bf16.bf16.f32 "
        "{%0,%1,%2,%3}, {%4,%5,%6,%7}, {%8,%9}, {%0,%1,%2,%3};"
        : "+f"(c[0]), "+f"(c[1]), "+f"(c[2]), "+f"(c[3])
        : "r"(a[0]), "r"(a[1]), "r"(a[2]), "r"(a[3]), "r"(b0), "r"(b1));
}

// ---------------- RoPE tables ------------------------------------------------
__global__ void rope_table_kernel() {
    int idx = blockIdx.x * blockDim.x + threadIdx.x;
    if (idx >= CS*32) return;
    int p = idx >> 5;
    int j = idx & 31;
    double expo = (double)(2*j) / 64.0;
    double freq = exp(-expo * log(10000.0));
    double ang  = (double)p * freq;
    g_cos[idx] = (float)cos(ang);
    g_sin[idx] = (float)sin(ang);
}

__global__ void rope_apply_kernel(const int* __restrict__ posids) {
    int idx = blockIdx.x * blockDim.x + threadIdx.x;
    int j  = idx & 31;
    int s  = (idx >> 5) & (CS - 1);
    int bh = idx >> 17;
    int b  = bh >> 4;
    int p  = posids[b*CS + s];
    float c  = g_cos[p*32 + j];
    float sn = g_sin[p*32 + j];
    size_t base = ((size_t)bh*CS + (size_t)s)*CHD + j;
    float q1 = g_q[base], q2 = g_q[base+32];
    g_q[base]    = q1*c - q2*sn;
    g_q[base+32] = q2*c + q1*sn;
    float k1 = g_k[base], k2 = g_k[base+32];
    g_k[base]    = k1*c - k2*sn;
    g_k[base+32] = k2*c + k1*sn;
}

// ---------------- fp32 -> bf16 hi/lo split (row-major A) ---------------------
// use_attn != 0: read from device-global g_attn (resolved DEVICE-side; passing
// the __device__ symbol as a host-side kernel arg silently binds the host
// shadow via ATS and reads zeros -- the R8 bug).
__global__ void conv_split_kernel(const float* __restrict__ src, int use_attn) {
    const float* p = use_attn ? (const float*)g_attn : src;
    int i = blockIdx.x * blockDim.x + threadIdx.x;
    size_t base = (size_t)i * 4;
    float4 v = *(const float4*)(p + base);
    __nv_bfloat16 h0 = __float2bfloat16(v.x);
    __nv_bfloat16 h1 = __float2bfloat16(v.y);
    __nv_bfloat16 h2 = __float2bfloat16(v.z);
    __nv_bfloat16 h3 = __float2bfloat16(v.w);
    __nv_bfloat16 l0 = __float2bfloat16(v.x - __bfloat162float(h0));
    __nv_bfloat16 l1 = __float2bfloat16(v.y - __bfloat162float(h1));
    __nv_bfloat16 l2 = __float2bfloat16(v.z - __bfloat162float(h2));
    __nv_bfloat16 l3 = __float2bfloat16(v.w - __bfloat162float(h3));
    *(__nv_bfloat162*)(g_Ah + base)     = __nv_bfloat162(h0, h1);
    *(__nv_bfloat162*)(g_Ah + base + 2) = __nv_bfloat162(h2, h3);
    *(__nv_bfloat162*)(g_Al + base)     = __nv_bfloat162(l0, l1);
    *(__nv_bfloat162*)(g_Al + base + 2) = __nv_bfloat162(l2, l3);
}

// ---------------- weights: fp32 [k][n] -> bf16 hi/lo transposed [n][k] -------
__global__ void conv_w_kernel(const float* __restrict__ w0, const float* __restrict__ w1,
                              const float* __restrict__ w2, const float* __restrict__ w3) {
    __shared__ float t[32][33];
    int wz = blockIdx.z;
    const float* W = (wz == 0) ? w0 : (wz == 1) ? w1 : (wz == 2) ? w2 : w3;
    int n0 = blockIdx.x * 32, k0 = blockIdx.y * 32;
    int tx = threadIdx.x, ty = threadIdx.y;   // 32 x 8
#pragma unroll
    for (int r = 0; r < 4; r++) {
        int k = ty + r*8;
        t[k][tx] = W[(size_t)(k0 + k)*CD + n0 + tx];
    }
    __syncthreads();
    size_t off = (size_t)wz * CD * CD;
#pragma unroll
    for (int r = 0; r < 4; r++) {
        int nn = ty + r*8;
        float x = t[tx][nn];
        __nv_bfloat16 h = __float2bfloat16(x);
        __nv_bfloat16 l = __float2bfloat16(x - __bfloat162float(h));
        g_Wh[off + (size_t)(n0 + nn)*CD + k0 + tx] = h;
        g_Wl[off + (size_t)(n0 + nn)*CD + k0 + tx] = l;
    }
}

// ---------------- split-bf16 GEMM via mma.sync (m16n8k16) --------------------
// C[8192x1024] = A @ W ; A = g_Ah + g_Al, W^T = g_Wh + g_Wl stored [n][k]
// C ~= Ah*Bh + Ah*Bl + Al*Bh
// CTA 128x128, 256 thr, 8 warps (2m x 4n), warp tile 64x32
#define G_TILE    16384                     /* one 128x64 bf16 tile (SW128)    */
#define G_STAGE   (4*G_TILE)                /* Ah,Al,Bh,Bl                     */
#define G_SMEM    (1024 + 2*G_STAGE)

__device__ __forceinline__ void g_load_stage(uint32_t dat, int s, int m0, int n0, int tid,
                                             const __nv_bfloat16* Bh, const __nv_bfloat16* Bl) {
    uint32_t buf = dat + (uint32_t)(s & 1) * G_STAGE;
    int k0 = s * 64;
#pragma unroll
    for (int i = 0; i < 4; i++) {
        int cc  = tid + 256*i;
        int row = cc >> 3;
        int kc  = cc & 7;
        uint32_t d = SWZ(row*128 + kc*16);
        size_t ea = (size_t)(m0 + row)*CD + k0 + kc*8;
        size_t eb = (size_t)(n0 + row)*CD + k0 + kc*8;
        CP16(buf + d,             g_Ah + ea);
        CP16(buf + G_TILE + d,    g_Al + ea);
        CP16(buf + 2*G_TILE + d,  Bh + eb);
        CP16(buf + 3*G_TILE + d,  Bl + eb);
    }
    asm volatile("cp.async.commit_group;" ::: "memory");
}

__global__ __launch_bounds__(256) void gemm_tc(int widx, float* __restrict__ outp, int mode) {
    extern __shared__ char smem_raw[];
    uint32_t sb_raw = smem_u32(smem_raw);
    uint32_t dat = (sb_raw + 1023u) & ~1023u;     // 1024B-aligned tile region

    const int tid  = threadIdx.x;
    const int wid  = tid >> 5, lane = tid & 31;
    const int wm   = wid >> 2;          // 0..1 -> m rows wm*64
    const int wn   = wid & 3;           // 0..3 -> n cols wn*32
    const int m0 = blockIdx.x * 128, n0 = blockIdx.y * 128;

    const __nv_bfloat16* Bh = g_Wh + ((size_t)widx << 20);
    const __nv_bfloat16* Bl = g_Wl + ((size_t)widx << 20);

    float acc[4][4][4];
#pragma unroll
    for (int mt = 0; mt < 4; mt++)
#pragma unroll
        for (int nt = 0; nt < 4; nt++)
#pragma unroll
            for (int e = 0; e < 4; e++) acc[mt][nt][e] = 0.f;

    // ldmatrix per-lane addressing: g = lane>>3 selects (m8-half, k8-half)
    const int g  = lane >> 3, r = lane & 7;
    const int arow = wm*64 + (g & 1)*8 + r;          // + mt*16
    const int brow = wn*32 + (g & 1)*8 + r;          // + ng*16
    const int kcol = (g >> 1) * 16;                  // byte offset in k16 step

    g_load_stage(dat, 0, m0, n0, tid, Bh, Bl);

    for (int s = 0; s < 16; s++) {
        if (s + 1 < 16) {
            g_load_stage(dat, s + 1, m0, n0, tid, Bh, Bl);
            asm volatile("cp.async.wait_group 1;" ::: "memory");
        } else {
            asm volatile("cp.async.wait_group 0;" ::: "memory");
        }
        __syncthreads();

        uint32_t buf = dat + (uint32_t)(s & 1) * G_STAGE;
        uint32_t tAh = buf, tAl = buf + G_TILE, tBh = buf + 2*G_TILE, tBl = buf + 3*G_TILE;

#pragma unroll
        for (int ks = 0; ks < 4; ks++) {
            const int kb = ks*32 + kcol;
            uint32_t a[4][4], bhf[2][4], blf[2][4];
#pragma unroll
            for (int mt = 0; mt < 4; mt++)
                ldsm4(a[mt], tAh + SWZ((arow + mt*16)*128 + kb));
#pragma unroll
            for (int ng = 0; ng < 2; ng++) {
                ldsm4(bhf[ng], tBh + SWZ((brow + ng*16)*128 + kb));
                ldsm4(blf[ng], tBl + SWZ((brow + ng*16)*128 + kb));
            }
            // Ah*Bh and Ah*Bl
#pragma unroll
            for (int mt = 0; mt < 4; mt++)
#pragma unroll
                for (int nt = 0; nt < 4; nt++) {
                    int ng = nt >> 1, j = nt & 1;
                    mma_bf16(acc[mt][nt], a[mt], bhf[ng][j], bhf[ng][j+2]);
                    mma_bf16(acc[mt][nt], a[mt], blf[ng][j], blf[ng][j+2]);
                }
            // Al*Bh (reuse A regs)
#pragma unroll
            for (int mt = 0; mt < 4; mt++)
                ldsm4(a[mt], tAl + SWZ((arow + mt*16)*128 + kb));
#pragma unroll
            for (int mt = 0; mt < 4; mt++)
#pragma unroll
                for (int nt = 0; nt < 4; nt++) {
                    int ng = nt >> 1, j = nt & 1;
                    mma_bf16(acc[mt][nt], a[mt], bhf[ng][j], bhf[ng][j+2]);
                }
        }
        __syncthreads();
    }

    // epilogue: write accumulators (C frag: lane = gid*4+tig; rows gid/gid+8, cols tig*2)
    const int gid = lane >> 2, tig = lane & 3;
    const int b_ = m0 >> 12;
    float* dst = (mode == 0) ? g_q : (mode == 1) ? g_k : g_v;
#pragma unroll
    for (int mt = 0; mt < 4; mt++) {
#pragma unroll
        for (int nt = 0; nt < 4; nt++) {
            int mrow = m0 + wm*64 + mt*16 + gid;
            int ncol = n0 + wn*32 + nt*8 + tig*2;
#pragma unroll
            for (int half = 0; half < 2; half++) {
                int m = mrow + half*8;
                float2 val = make_float2(acc[mt][nt][half*2], acc[mt][nt][half*2 + 1]);
                if (mode == 3) {
                    *(float2*)(outp + (size_t)m*CD + ncol) = val;
                } else {
                    int h  = ncol >> 6, hd = ncol & 63;
                    int s_ = m & (CS - 1);
                    *(float2*)(dst + (((size_t)(b_*CH + h))*CS + s_)*CHD + hd) = val;
                }
            }
        }
    }
}

// ---------------- block-sparse flash attention (unchanged) -------------------
#define PADA 65
#define PADV 68
#define ATTN_SMEM_BYTES ((64*PADA*3 + 64*PADV) * 4)

__global__ __launch_bounds__(128) void attn_kernel() {
    extern __shared__ float sm[];
    float* qs = sm;
    float* ks = qs + 64*PADA;
    float* vs = ks + 64*PADA;
    float* ps = vs + 64*PADV;

    const int n   = blockIdx.x;
    const int bh  = blockIdx.y;
    const int tid = threadIdx.x;
    const int ty  = tid >> 3;
    const int tx  = tid & 7;
    const int q0  = ty*4;

    const float* qsrc = g_q + ((size_t)bh*CS + (size_t)n*64)*CHD;
#pragma unroll
    for (int r = 0; r < 8; r++) {
        int idx = tid + 128*r;
        int row = idx >> 4;
        int col = (idx & 15) << 2;
        float4 v = *(const float4*)(qsrc + row*CHD + col);
        float* d = qs + row*PADA + col;
        d[0]=v.x; d[1]=v.y; d[2]=v.z; d[3]=v.w;
    }

    float m_i[4], l_i[4], acc[4][8];
#pragma unroll
    for (int i = 0; i < 4; i++) {
        m_i[i] = -1e30f; l_i[i] = 0.f;
#pragma unroll
        for (int c = 0; c < 8; c++) acc[i][c] = 0.f;
    }

    for (int w = 0; w < CW; w++) {
        int kb = n - (CW-1) + w;
        if (kb < 0) continue;
        __syncthreads();

        const float* ksrc = g_k + ((size_t)bh*CS + (size_t)kb*64)*CHD;
        const float* vsrc = g_v + ((size_t)bh*CS + (size_t)kb*64)*CHD;
#pragma unroll
        for (int r = 0; r < 8; r++) {
            int idx = tid + 128*r;
            int row = idx >> 4;
            int col = (idx & 15) << 2;
            float4 kv = *(const float4*)(ksrc + row*CHD + col);
            float* kd = ks + row*PADA + col;
            kd[0]=kv.x; kd[1]=kv.y; kd[2]=kv.z; kd[3]=kv.w;
            float4 vv = *(const float4*)(vsrc + row*CHD + col);
            *(float4*)(vs + row*PADV + col) = vv;
        }
        __syncthreads();

        float sc[4][8];
#pragma unroll
        for (int i = 0; i < 4; i++)
#pragma unroll
            for (int jj = 0; jj < 8; jj++) sc[i][jj] = 0.f;

#pragma unroll 4
        for (int d = 0; d < 64; d++) {
            float rq[4];
#pragma unroll
            for (int i = 0; i < 4; i++) rq[i] = qs[(q0+i)*PADA + d];
            float rk[8];
#pragma unroll
            for (int jj = 0; jj < 8; jj++) rk[jj] = ks[(jj*8+tx)*PADA + d];
#pragma unroll
            for (int i = 0; i < 4; i++)
#pragma unroll
                for (int jj = 0; jj < 8; jj++)
                    sc[i][jj] = fmaf(rq[i], rk[jj], sc[i][jj]);
        }

        const bool diag = (kb == n);
#pragma unroll
        for (int i = 0; i < 4; i++) {
            int qi = q0 + i;
#pragma unroll
            for (int jj = 0; jj < 8; jj++) {
                float v = sc[i][jj] * 0.125f;
                if (diag && (jj*8 + tx) > qi) v = -1e30f;
                sc[i][jj] = v;
            }
        }

#pragma unroll
        for (int i = 0; i < 4; i++) {
            float mb = sc[i][0];
#pragma unroll
            for (int jj = 1; jj < 8; jj++) mb = fmaxf(mb, sc[i][jj]);
#pragma unroll
            for (int o = 1; o < 8; o <<= 1)
                mb = fmaxf(mb, __shfl_xor_sync(0xffffffffu, mb, o));
            float mn   = fmaxf(m_i[i], mb);
            float corr = __expf(m_i[i] - mn);
            float rs = 0.f;
#pragma unroll
            for (int jj = 0; jj < 8; jj++) {
                float p = __expf(sc[i][jj] - mn);
                sc[i][jj] = p;
                rs += p;
            }
#pragma unroll
            for (int o = 1; o < 8; o <<= 1)
                rs += __shfl_xor_sync(0xffffffffu, rs, o);
            l_i[i] = l_i[i]*corr + rs;
            m_i[i] = mn;
#pragma unroll
            for (int c = 0; c < 8; c++) acc[i][c] *= corr;
#pragma unroll
            for (int jj = 0; jj < 8; jj++)
                ps[(q0+i)*PADA + jj*8 + tx] = sc[i][jj];
        }
        __syncthreads();

#pragma unroll 2
        for (int j = 0; j < 64; j++) {
            float rp[4];
#pragma unroll
            for (int i = 0; i < 4; i++) rp[i] = ps[(q0+i)*PADA + j];
            float4 v0 = *(float4*)(vs + j*PADV + tx*8);
            float4 v1 = *(float4*)(vs + j*PADV + tx*8 + 4);
#pragma unroll
            for (int i = 0; i < 4; i++) {
                acc[i][0] = fmaf(rp[i], v0.x, acc[i][0]);
                acc[i][1] = fmaf(rp[i], v0.y, acc[i][1]);
                acc[i][2] = fmaf(rp[i], v0.z, acc[i][2]);
                acc[i][3] = fmaf(rp[i], v0.w, acc[i][3]);
                acc[i][4] = fmaf(rp[i], v1.x, acc[i][4]);
                acc[i][5] = fmaf(rp[i], v1.y, acc[i][5]);
                acc[i][6] = fmaf(rp[i], v1.z, acc[i][6]);
                acc[i][7] = fmaf(rp[i], v1.w, acc[i][7]);
            }
        }
    }

    const int b = bh >> 4;
    const int h = bh & 15;
#pragma unroll
    for (int i = 0; i < 4; i++) {
        float inv = 1.0f / l_i[i];
        int srow  = n*64 + q0 + i;
        float* o = g_attn + ((size_t)b*CS + srow)*CD + h*CHD + tx*8;
        float4 o0 = make_float4(acc[i][0]*inv, acc[i][1]*inv, acc[i][2]*inv, acc[i][3]*inv);
        float4 o1 = make_float4(acc[i][4]*inv, acc[i][5]*inv, acc[i][6]*inv, acc[i][7]*inv);
        *(float4*)o     = o0;
        *(float4*)(o+4) = o1;
    }
}

// ---------------- launch -----------------------------------------------------
extern "C" void kernel_launch(void* const* d_in, const int* in_sizes, int n_in,
                              void* d_out, int out_size) {
    const float* hidden = (const float*)d_in[0];
    const int*   posids = (const int*)d_in[1];
    const float* wq = (const float*)d_in[2];
    const float* wk = (const float*)d_in[3];
    const float* wv = (const float*)d_in[4];
    const float* wo = (const float*)d_in[5];
    float* out = (float*)d_out;

    cudaFuncSetAttribute(gemm_tc, cudaFuncAttributeMaxDynamicSharedMemorySize, G_SMEM);
    cudaFuncSetAttribute(attn_kernel, cudaFuncAttributeMaxDynamicSharedMemorySize, ATTN_SMEM_BYTES);

    conv_w_kernel<<<dim3(32, 32, 4), dim3(32, 8)>>>(wq, wk, wv, wo);
    conv_split_kernel<<<(CM*CD/4)/256, 256>>>(hidden, 0);
    rope_table_kernel<<<(CS*32 + 255)/256, 256>>>();

    dim3 ggrid(CM/128, CD/128);   // (64, 8)
    gemm_tc<<<ggrid, 256, G_SMEM>>>(0, nullptr, 0);
    gemm_tc<<<ggrid, 256, G_SMEM>>>(1, nullptr, 1);
    gemm_tc<<<ggrid, 256, G_SMEM>>>(2, nullptr, 2);

    rope_apply_kernel<<<(CB*CH*CS*32)/256, 256>>>(posids);

    attn_kernel<<<dim3(CNB, CB*CH), 128, ATTN_SMEM_BYTES>>>();

    conv_split_kernel<<<(CM*CD/4)/256, 256>>>(nullptr, 1);
    gemm_tc<<<ggrid, 256, G_SMEM>>>(3, out, 3);
}

// round 11
// speedup vs baseline: 2.9884x; 1.5476x over previous
#include <cuda_runtime.h>
#include <cuda_bf16.h>
#include <cuda_fp16.h>
#include <cstdint>
#include <math.h>

#define CB   2
#define CS   4096
#define CD   1024
#define CH   16
#define CHD  64
#define CNB  64
#define CW   8
#define CM   (CB*CS)

// ---------------- scratch (device globals) ----------------------------------
__device__ float g_q[(size_t)CB*CH*CS*CHD];
__device__ float g_k[(size_t)CB*CH*CS*CHD];
__device__ float g_v[(size_t)CB*CH*CS*CHD];
__device__ float g_attn[(size_t)CB*CS*CD];
__device__ float g_cos[CS*32];
__device__ float g_sin[CS*32];
__device__ __align__(256) __nv_bfloat16 g_Ah[(size_t)CM*CD];
__device__ __align__(256) __nv_bfloat16 g_Al[(size_t)CM*CD];
__device__ __align__(256) __nv_bfloat16 g_Wh[(size_t)4*CD*CD];   // [n][k] transposed
__device__ __align__(256) __nv_bfloat16 g_Wl[(size_t)4*CD*CD];
__device__ __align__(256) __half g_q16[(size_t)CB*CH*CS*CHD];    // (bh,s,hd)
__device__ __align__(256) __half g_k16[(size_t)CB*CH*CS*CHD];    // (bh,s,hd)
__device__ __align__(256) __half g_vt [(size_t)CB*CH*CHD*CS];    // (bh,hd,s)

// ---------------- helpers ----------------------------------------------------
__device__ __forceinline__ uint32_t smem_u32(const void* p) {
    uint32_t a;
    asm("{ .reg .u64 t; cvta.to.shared.u64 t, %1; cvt.u32.u64 %0, t; }" : "=r"(a) : "l"(p));
    return a;
}
#define SWZ(o) ((o) ^ (((o) >> 3) & 0x70))

#define CP16(d, s) \
    asm volatile("cp.async.cg.shared.global [%0], [%1], 16;" :: "r"((uint32_t)(d)), "l"(s) : "memory")

__device__ __forceinline__ void ldsm4(uint32_t* r, uint32_t addr) {
    asm volatile("ldmatrix.sync.aligned.m8n8.x4.shared.b16 {%0,%1,%2,%3}, [%4];"
        : "=r"(r[0]), "=r"(r[1]), "=r"(r[2]), "=r"(r[3]) : "r"(addr));
}

__device__ __forceinline__ void mma_bf16(float* c, const uint32_t* a, uint32_t b0, uint32_t b1) {
    asm volatile("mma.sync.aligned.m16n8k16.row.col.f32.bf16.bf16.f32 "
        "{%0,%1,%2,%3}, {%4,%5,%6,%7}, {%8,%9}, {%0,%1,%2,%3};"
        : "+f"(c[0]), "+f"(c[1]), "+f"(c[2]), "+f"(c[3])
        : "r"(a[0]), "r"(a[1]), "r"(a[2]), "r"(a[3]), "r"(b0), "r"(b1));
}

__device__ __forceinline__ void mma_f16(float* c, const uint32_t* a, uint32_t b0, uint32_t b1) {
    asm volatile("mma.sync.aligned.m16n8k16.row.col.f32.f16.f16.f32 "
        "{%0,%1,%2,%3}, {%4,%5,%6,%7}, {%8,%9}, {%0,%1,%2,%3};"
        : "+f"(c[0]), "+f"(c[1]), "+f"(c[2]), "+f"(c[3])
        : "r"(a[0]), "r"(a[1]), "r"(a[2]), "r"(a[3]), "r"(b0), "r"(b1));
}

// exp2 without MUFU: magic-number round + deg-5 poly + exponent splice.
__device__ __forceinline__ float exp2p(float y) {
    y = fmaxf(y, -126.0f);
    float t = y + 12582912.0f;           // 1.5*2^23: rint via FADD
    int   n = __float_as_int(t) - 0x4B400000;
    float f = y - (t - 12582912.0f);     // f in [-0.5, 0.5]
    float p = 0.0013333558f;
    p = fmaf(p, f, 0.0096181291f);
    p = fmaf(p, f, 0.0555041087f);
    p = fmaf(p, f, 0.2402265069f);
    p = fmaf(p, f, 0.6931471806f);
    p = fmaf(p, f, 1.0f);
    return p * __int_as_float((n + 127) << 23);
}

__device__ __forceinline__ uint32_t pack_h2(float a, float b) {
    __half2 h = __floats2half2_rn(a, b);
    return *reinterpret_cast<uint32_t*>(&h);
}

// ---------------- RoPE tables ------------------------------------------------
__global__ void rope_table_kernel() {
    int idx = blockIdx.x * blockDim.x + threadIdx.x;
    if (idx >= CS*32) return;
    int p = idx >> 5;
    int j = idx & 31;
    double expo = (double)(2*j) / 64.0;
    double freq = exp(-expo * log(10000.0));
    double ang  = (double)p * freq;
    g_cos[idx] = (float)cos(ang);
    g_sin[idx] = (float)sin(ang);
}

// RoPE: read fp32 q/k, write ONLY fp16 copies (attention consumes fp16)
__global__ void rope_apply_kernel(const int* __restrict__ posids) {
    int idx = blockIdx.x * blockDim.x + threadIdx.x;
    int j  = idx & 31;
    int s  = (idx >> 5) & (CS - 1);
    int bh = idx >> 17;
    int b  = bh >> 4;
    int p  = posids[b*CS + s];
    float c  = g_cos[p*32 + j];
    float sn = g_sin[p*32 + j];
    size_t base = ((size_t)bh*CS + (size_t)s)*CHD + j;
    float q1 = g_q[base], q2 = g_q[base+32];
    g_q16[base]    = __float2half(q1*c - q2*sn);
    g_q16[base+32] = __float2half(q2*c + q1*sn);
    float k1 = g_k[base], k2 = g_k[base+32];
    g_k16[base]    = __float2half(k1*c - k2*sn);
    g_k16[base+32] = __float2half(k2*c + k1*sn);
}

// V: fp32 (bh,s,hd) -> fp16 transposed (bh,hd,s)
__global__ void conv_vt_kernel() {
    __shared__ float t[32][33];
    int bh = blockIdx.z;
    int s0 = blockIdx.x * 32;
    int h0 = blockIdx.y * 32;
    int tx = threadIdx.x, ty = threadIdx.y;   // 32 x 8
#pragma unroll
    for (int r = 0; r < 4; r++)
        t[ty + 8*r][tx] = g_v[((size_t)bh*CS + s0 + ty + 8*r)*CHD + h0 + tx];
    __syncthreads();
#pragma unroll
    for (int r = 0; r < 4; r++)
        g_vt[((size_t)bh*CHD + h0 + ty + 8*r)*CS + s0 + tx] = __float2half(t[tx][ty + 8*r]);
}

// ---------------- fp32 -> bf16 hi/lo split (row-major A) ---------------------
__global__ void conv_split_kernel(const float* __restrict__ src, int use_attn) {
    const float* p = use_attn ? (const float*)g_attn : src;
    int i = blockIdx.x * blockDim.x + threadIdx.x;
    size_t base = (size_t)i * 4;
    float4 v = *(const float4*)(p + base);
    __nv_bfloat16 h0 = __float2bfloat16(v.x);
    __nv_bfloat16 h1 = __float2bfloat16(v.y);
    __nv_bfloat16 h2 = __float2bfloat16(v.z);
    __nv_bfloat16 h3 = __float2bfloat16(v.w);
    __nv_bfloat16 l0 = __float2bfloat16(v.x - __bfloat162float(h0));
    __nv_bfloat16 l1 = __float2bfloat16(v.y - __bfloat162float(h1));
    __nv_bfloat16 l2 = __float2bfloat16(v.z - __bfloat162float(h2));
    __nv_bfloat16 l3 = __float2bfloat16(v.w - __bfloat162float(h3));
    *(__nv_bfloat162*)(g_Ah + base)     = __nv_bfloat162(h0, h1);
    *(__nv_bfloat162*)(g_Ah + base + 2) = __nv_bfloat162(h2, h3);
    *(__nv_bfloat162*)(g_Al + base)     = __nv_bfloat162(l0, l1);
    *(__nv_bfloat162*)(g_Al + base + 2) = __nv_bfloat162(l2, l3);
}

// ---------------- weights: fp32 [k][n] -> bf16 hi/lo transposed [n][k] -------
__global__ void conv_w_kernel(const float* __restrict__ w0, const float* __restrict__ w1,
                              const float* __restrict__ w2, const float* __restrict__ w3) {
    __shared__ float t[32][33];
    int wz = blockIdx.z;
    const float* W = (wz == 0) ? w0 : (wz == 1) ? w1 : (wz == 2) ? w2 : w3;
    int n0 = blockIdx.x * 32, k0 = blockIdx.y * 32;
    int tx = threadIdx.x, ty = threadIdx.y;   // 32 x 8
#pragma unroll
    for (int r = 0; r < 4; r++) {
        int k = ty + r*8;
        t[k][tx] = W[(size_t)(k0 + k)*CD + n0 + tx];
    }
    __syncthreads();
    size_t off = (size_t)wz * CD * CD;
#pragma unroll
    for (int r = 0; r < 4; r++) {
        int nn = ty + r*8;
        float x = t[tx][nn];
        __nv_bfloat16 h = __float2bfloat16(x);
        __nv_bfloat16 l = __float2bfloat16(x - __bfloat162float(h));
        g_Wh[off + (size_t)(n0 + nn)*CD + k0 + tx] = h;
        g_Wl[off + (size_t)(n0 + nn)*CD + k0 + tx] = l;
    }
}

// ---------------- split-bf16 GEMM via mma.sync (m16n8k16) --------------------
#define G_TILE    16384
#define G_STAGE   (4*G_TILE)
#define G_SMEM    (1024 + 2*G_STAGE)

__device__ __forceinline__ void g_load_stage(uint32_t dat, int s, int m0, int n0, int tid,
                                             const __nv_bfloat16* Bh, const __nv_bfloat16* Bl) {
    uint32_t buf = dat + (uint32_t)(s & 1) * G_STAGE;
    int k0 = s * 64;
#pragma unroll
    for (int i = 0; i < 4; i++) {
        int cc  = tid + 256*i;
        int row = cc >> 3;
        int kc  = cc & 7;
        uint32_t d = SWZ(row*128 + kc*16);
        size_t ea = (size_t)(m0 + row)*CD + k0 + kc*8;
        size_t eb = (size_t)(n0 + row)*CD + k0 + kc*8;
        CP16(buf + d,             g_Ah + ea);
        CP16(buf + G_TILE + d,    g_Al + ea);
        CP16(buf + 2*G_TILE + d,  Bh + eb);
        CP16(buf + 3*G_TILE + d,  Bl + eb);
    }
    asm volatile("cp.async.commit_group;" ::: "memory");
}

__global__ __launch_bounds__(256) void gemm_tc(int widx, float* __restrict__ outp, int mode) {
    extern __shared__ char smem_raw[];
    uint32_t sb_raw = smem_u32(smem_raw);
    uint32_t dat = (sb_raw + 1023u) & ~1023u;

    const int tid  = threadIdx.x;
    const int wid  = tid >> 5, lane = tid & 31;
    const int wm   = wid >> 2;
    const int wn   = wid & 3;
    const int m0 = blockIdx.x * 128, n0 = blockIdx.y * 128;

    const __nv_bfloat16* Bh = g_Wh + ((size_t)widx << 20);
    const __nv_bfloat16* Bl = g_Wl + ((size_t)widx << 20);

    float acc[4][4][4];
#pragma unroll
    for (int mt = 0; mt < 4; mt++)
#pragma unroll
        for (int nt = 0; nt < 4; nt++)
#pragma unroll
            for (int e = 0; e < 4; e++) acc[mt][nt][e] = 0.f;

    const int g  = lane >> 3, r = lane & 7;
    const int arow = wm*64 + (g & 1)*8 + r;
    const int brow = wn*32 + (g & 1)*8 + r;
    const int kcol = (g >> 1) * 16;

    g_load_stage(dat, 0, m0, n0, tid, Bh, Bl);

    for (int s = 0; s < 16; s++) {
        if (s + 1 < 16) {
            g_load_stage(dat, s + 1, m0, n0, tid, Bh, Bl);
            asm volatile("cp.async.wait_group 1;" ::: "memory");
        } else {
            asm volatile("cp.async.wait_group 0;" ::: "memory");
        }
        __syncthreads();

        uint32_t buf = dat + (uint32_t)(s & 1) * G_STAGE;
        uint32_t tAh = buf, tAl = buf + G_TILE, tBh = buf + 2*G_TILE, tBl = buf + 3*G_TILE;

#pragma unroll
        for (int ks = 0; ks < 4; ks++) {
            const int kb = ks*32 + kcol;
            uint32_t a[4][4], bhf[2][4], blf[2][4];
#pragma unroll
            for (int mt = 0; mt < 4; mt++)
                ldsm4(a[mt], tAh + SWZ((arow + mt*16)*128 + kb));
#pragma unroll
            for (int ng = 0; ng < 2; ng++) {
                ldsm4(bhf[ng], tBh + SWZ((brow + ng*16)*128 + kb));
                ldsm4(blf[ng], tBl + SWZ((brow + ng*16)*128 + kb));
            }
#pragma unroll
            for (int mt = 0; mt < 4; mt++)
#pragma unroll
                for (int nt = 0; nt < 4; nt++) {
                    int ng = nt >> 1, j = nt & 1;
                    mma_bf16(acc[mt][nt], a[mt], bhf[ng][j], bhf[ng][j+2]);
                    mma_bf16(acc[mt][nt], a[mt], blf[ng][j], blf[ng][j+2]);
                }
#pragma unroll
            for (int mt = 0; mt < 4; mt++)
                ldsm4(a[mt], tAl + SWZ((arow + mt*16)*128 + kb));
#pragma unroll
            for (int mt = 0; mt < 4; mt++)
#pragma unroll
                for (int nt = 0; nt < 4; nt++) {
                    int ng = nt >> 1, j = nt & 1;
                    mma_bf16(acc[mt][nt], a[mt], bhf[ng][j], bhf[ng][j+2]);
                }
        }
        __syncthreads();
    }

    const int gid = lane >> 2, tig = lane & 3;
    const int b_ = m0 >> 12;
    float* dst = (mode == 0) ? g_q : (mode == 1) ? g_k : g_v;
#pragma unroll
    for (int mt = 0; mt < 4; mt++) {
#pragma unroll
        for (int nt = 0; nt < 4; nt++) {
            int mrow = m0 + wm*64 + mt*16 + gid;
            int ncol = n0 + wn*32 + nt*8 + tig*2;
#pragma unroll
            for (int half = 0; half < 2; half++) {
                int m = mrow + half*8;
                float2 val = make_float2(acc[mt][nt][half*2], acc[mt][nt][half*2 + 1]);
                if (mode == 3) {
                    *(float2*)(outp + (size_t)m*CD + ncol) = val;
                } else {
                    int h  = ncol >> 6, hd = ncol & 63;
                    int s_ = m & (CS - 1);
                    *(float2*)(dst + (((size_t)(b_*CH + h))*CS + s_)*CHD + hd) = val;
                }
            }
        }
    }
}

// ---------------- fp16 tensor-core flash attention ---------------------------
// CTA: 128 thr (4 warps), one 64-row q-block x one (b,h). Warp w: q rows w*16..+15.
// smem: Q tile 8KB + double-buffered {K tile 8KB, V^T tile 8KB}.
#define AT_TILE   8192
#define AT_SMEM   (1024 + 5*AT_TILE)

__device__ __forceinline__ void at_stage(uint32_t kbuf, const __half* ksrc,
                                         const __half* vtsrc, int tid) {
#pragma unroll
    for (int i = 0; i < 4; i++) {
        int cc  = tid + 128*i;
        int row = cc >> 3;
        int kc  = cc & 7;
        uint32_t d = SWZ(row*128 + kc*16);
        CP16(kbuf + d,           ksrc  + (size_t)row*CHD + kc*8);
        CP16(kbuf + AT_TILE + d, vtsrc + (size_t)row*CS  + kc*8);
    }
    asm volatile("cp.async.commit_group;" ::: "memory");
}

__global__ __launch_bounds__(128) void attn_tc_kernel() {
    extern __shared__ char sraw[];
    uint32_t dat = (smem_u32(sraw) + 1023u) & ~1023u;

    const int n   = blockIdx.x;
    const int bh  = blockIdx.y;
    const int tid = threadIdx.x;
    const int w   = tid >> 5, lane = tid & 31;
    const int g   = lane >> 3, r = lane & 7;
    const int gid = lane >> 2, tig = lane & 3;

    // stage Q (one commit together with first K/VT stage group is fine too,
    // but give Q its own group then first stage -- both drained by wait 0)
    const __half* qsrc = g_q16 + ((size_t)bh*CS + (size_t)n*64)*CHD;
#pragma unroll
    for (int i = 0; i < 4; i++) {
        int cc = tid + 128*i;
        int row = cc >> 3;
        int kc  = cc & 7;
        CP16(dat + SWZ(row*128 + kc*16), qsrc + (size_t)row*CHD + kc*8);
    }
    asm volatile("cp.async.commit_group;" ::: "memory");

    const int kb0 = (n - (CW-1) < 0) ? 0 : n - (CW-1);
    const int nk  = n - kb0 + 1;
    const __half* kbase_g  = g_k16 + ((size_t)bh*CS)*CHD;
    const __half* vtbase_g = g_vt  + ((size_t)bh*CHD)*CS;

    at_stage(dat + AT_TILE, kbase_g + (size_t)kb0*64*CHD, vtbase_g + kb0*64, tid);

    float oacc[8][4];
#pragma unroll
    for (int nt = 0; nt < 8; nt++)
#pragma unroll
        for (int e = 0; e < 4; e++) oacc[nt][e] = 0.f;
    float m0 = -1e30f, m1 = -1e30f, l0 = 0.f, l1 = 0.f;
    uint32_t qf[4][4];

    const float SCL = 0.18033688011f;    // 0.125 * log2(e)
    const int ql0 = w*16 + gid, ql1 = ql0 + 8;

    for (int i = 0; i < nk; i++) {
        const int kb = kb0 + i;
        asm volatile("cp.async.wait_group 0;" ::: "memory");
        __syncthreads();

        if (i == 0) {
#pragma unroll
            for (int kc = 0; kc < 4; kc++)
                ldsm4(qf[kc], dat + SWZ((w*16 + (g&1)*8 + r)*128 + (g>>1)*16 + kc*32));
        }
        if (i + 1 < nk)
            at_stage(dat + AT_TILE + ((i+1)&1)*2*AT_TILE,
                     kbase_g + (size_t)(kb+1)*64*CHD, vtbase_g + (kb+1)*64, tid);

        const uint32_t kbuf = dat + AT_TILE + (i&1)*2*AT_TILE;
        const uint32_t vbuf = kbuf + AT_TILE;

        // ---- scores S = Q K^T (m16 x n64 per warp) ----
        float sacc[8][4];
#pragma unroll
        for (int nt = 0; nt < 8; nt++)
#pragma unroll
            for (int e = 0; e < 4; e++) sacc[nt][e] = 0.f;

#pragma unroll
        for (int kc = 0; kc < 4; kc++) {
            uint32_t kf[4][4];
#pragma unroll
            for (int ng = 0; ng < 4; ng++)
                ldsm4(kf[ng], kbuf + SWZ((ng*16 + (g&1)*8 + r)*128 + (g>>1)*16 + kc*32));
#pragma unroll
            for (int nt = 0; nt < 8; nt++)
                mma_f16(sacc[nt], qf[kc], kf[nt>>1][nt&1], kf[nt>>1][(nt&1)+2]);
        }

        // ---- scale to exp2 domain + causal mask on diagonal block ----
#pragma unroll
        for (int nt = 0; nt < 8; nt++)
#pragma unroll
            for (int e = 0; e < 4; e++) sacc[nt][e] *= SCL;
        if (kb == n) {
#pragma unroll
            for (int nt = 0; nt < 8; nt++) {
                int c0 = nt*8 + 2*tig, c1 = c0 + 1;
                if (c0 > ql0) sacc[nt][0] = -1e30f;
                if (c1 > ql0) sacc[nt][1] = -1e30f;
                if (c0 > ql1) sacc[nt][2] = -1e30f;
                if (c1 > ql1) sacc[nt][3] = -1e30f;
            }
        }

        // ---- online softmax (exp2 domain, no MUFU) ----
        float mx0 = -1e30f, mx1 = -1e30f;
#pragma unroll
        for (int nt = 0; nt < 8; nt++) {
            mx0 = fmaxf(mx0, fmaxf(sacc[nt][0], sacc[nt][1]));
            mx1 = fmaxf(mx1, fmaxf(sacc[nt][2], sacc[nt][3]));
        }
        mx0 = fmaxf(mx0, __shfl_xor_sync(0xffffffffu, mx0, 1));
        mx0 = fmaxf(mx0, __shfl_xor_sync(0xffffffffu, mx0, 2));
        mx1 = fmaxf(mx1, __shfl_xor_sync(0xffffffffu, mx1, 1));
        mx1 = fmaxf(mx1, __shfl_xor_sync(0xffffffffu, mx1, 2));
        float mn0 = fmaxf(m0, mx0), mn1 = fmaxf(m1, mx1);
        float cr0 = exp2p(m0 - mn0), cr1 = exp2p(m1 - mn1);
        m0 = mn0; m1 = mn1;
        float rs0 = 0.f, rs1 = 0.f;
#pragma unroll
        for (int nt = 0; nt < 8; nt++) {
            sacc[nt][0] = exp2p(sacc[nt][0] - mn0);
            sacc[nt][1] = exp2p(sacc[nt][1] - mn0);
            sacc[nt][2] = exp2p(sacc[nt][2] - mn1);
            sacc[nt][3] = exp2p(sacc[nt][3] - mn1);
            rs0 += sacc[nt][0] + sacc[nt][1];
            rs1 += sacc[nt][2] + sacc[nt][3];
        }
        rs0 += __shfl_xor_sync(0xffffffffu, rs0, 1);
        rs0 += __shfl_xor_sync(0xffffffffu, rs0, 2);
        rs1 += __shfl_xor_sync(0xffffffffu, rs1, 1);
        rs1 += __shfl_xor_sync(0xffffffffu, rs1, 2);
        l0 = l0*cr0 + rs0;
        l1 = l1*cr1 + rs1;
#pragma unroll
        for (int nt = 0; nt < 8; nt++) {
            oacc[nt][0] *= cr0; oacc[nt][1] *= cr0;
            oacc[nt][2] *= cr1; oacc[nt][3] *= cr1;
        }

        // ---- O += P V  (P A-frags assembled in-register from S frags) ----
#pragma unroll
        for (int kc = 0; kc < 4; kc++) {
            uint32_t pf[4];
            pf[0] = pack_h2(sacc[2*kc][0],   sacc[2*kc][1]);
            pf[1] = pack_h2(sacc[2*kc][2],   sacc[2*kc][3]);
            pf[2] = pack_h2(sacc[2*kc+1][0], sacc[2*kc+1][1]);
            pf[3] = pack_h2(sacc[2*kc+1][2], sacc[2*kc+1][3]);
            uint32_t vf[4][4];
#pragma unroll
            for (int ng = 0; ng < 4; ng++)
                ldsm4(vf[ng], vbuf + SWZ((ng*16 + (g&1)*8 + r)*128 + (g>>1)*16 + kc*32));
#pragma unroll
            for (int nt = 0; nt < 8; nt++)
                mma_f16(oacc[nt], pf, vf[nt>>1][nt&1], vf[nt>>1][(nt&1)+2]);
        }
        __syncthreads();
    }

    // ---- epilogue: normalize and write (b, s, h*64+hd) ----
    const float inv0 = 1.0f / l0, inv1 = 1.0f / l1;
    const int b = bh >> 4, h = bh & 15;
    const int srow = n*64 + w*16 + gid;
#pragma unroll
    for (int nt = 0; nt < 8; nt++) {
        int col = h*CHD + nt*8 + 2*tig;
        *(float2*)(g_attn + ((size_t)b*CS + srow)*CD + col) =
            make_float2(oacc[nt][0]*inv0, oacc[nt][1]*inv0);
        *(float2*)(g_attn + ((size_t)b*CS + srow + 8)*CD + col) =
            make_float2(oacc[nt][2]*inv1, oacc[nt][3]*inv1);
    }
}

// ---------------- launch -----------------------------------------------------
extern "C" void kernel_launch(void* const* d_in, const int* in_sizes, int n_in,
                              void* d_out, int out_size) {
    const float* hidden = (const float*)d_in[0];
    const int*   posids = (const int*)d_in[1];
    const float* wq = (const float*)d_in[2];
    const float* wk = (const float*)d_in[3];
    const float* wv = (const float*)d_in[4];
    const float* wo = (const float*)d_in[5];
    float* out = (float*)d_out;

    cudaFuncSetAttribute(gemm_tc, cudaFuncAttributeMaxDynamicSharedMemorySize, G_SMEM);
    cudaFuncSetAttribute(attn_tc_kernel, cudaFuncAttributeMaxDynamicSharedMemorySize, AT_SMEM);

    conv_w_kernel<<<dim3(32, 32, 4), dim3(32, 8)>>>(wq, wk, wv, wo);
    conv_split_kernel<<<(CM*CD/4)/256, 256>>>(hidden, 0);
    rope_table_kernel<<<(CS*32 + 255)/256, 256>>>();

    dim3 ggrid(CM/128, CD/128);
    gemm_tc<<<ggrid, 256, G_SMEM>>>(0, nullptr, 0);
    gemm_tc<<<ggrid, 256, G_SMEM>>>(1, nullptr, 1);
    gemm_tc<<<ggrid, 256, G_SMEM>>>(2, nullptr, 2);

    rope_apply_kernel<<<(CB*CH*CS*32)/256, 256>>>(posids);
    conv_vt_kernel<<<dim3(CS/32, CHD/32, CB*CH), dim3(32, 8)>>>();

    attn_tc_kernel<<<dim3(CNB, CB*CH), 128, AT_SMEM>>>();

    conv_split_kernel<<<(CM*CD/4)/256, 256>>>(nullptr, 1);
    gemm_tc<<<ggrid, 256, G_SMEM>>>(3, out, 3);
}

// round 12
// speedup vs baseline: 3.1345x; 1.0489x over previous
#include <cuda_runtime.h>
#include <cuda_bf16.h>
#include <cuda_fp16.h>
#include <cstdint>
#include <math.h>

#define CB   2
#define CS   4096
#define CD   1024
#define CH   16
#define CHD  64
#define CNB  64
#define CW   8
#define CM   (CB*CS)

// ---------------- scratch (device globals) ----------------------------------
__device__ float g_q[(size_t)CB*CH*CS*CHD];
__device__ float g_k[(size_t)CB*CH*CS*CHD];
__device__ float g_v[(size_t)CB*CH*CS*CHD];
__device__ float g_attn[(size_t)CB*CS*CD];
__device__ float g_cos[CS*32];
__device__ float g_sin[CS*32];
__device__ __align__(256) __nv_bfloat16 g_Ah[(size_t)CM*CD];
__device__ __align__(256) __nv_bfloat16 g_Al[(size_t)CM*CD];
__device__ __align__(256) __nv_bfloat16 g_Wh[(size_t)4*CD*CD];   // [n][k] transposed
__device__ __align__(256) __nv_bfloat16 g_Wl[(size_t)4*CD*CD];
__device__ __align__(256) __half g_q16[(size_t)CB*CH*CS*CHD];    // (bh,s,hd)
__device__ __align__(256) __half g_k16[(size_t)CB*CH*CS*CHD];    // (bh,s,hd)
__device__ __align__(256) __half g_vt [(size_t)CB*CH*CHD*CS];    // (bh,hd,s)

// ---------------- helpers ----------------------------------------------------
__device__ __forceinline__ uint32_t smem_u32(const void* p) {
    uint32_t a;
    asm("{ .reg .u64 t; cvta.to.shared.u64 t, %1; cvt.u32.u64 %0, t; }" : "=r"(a) : "l"(p));
    return a;
}
#define SWZ(o) ((o) ^ (((o) >> 3) & 0x70))

#define CP16(d, s) \
    asm volatile("cp.async.cg.shared.global [%0], [%1], 16;" :: "r"((uint32_t)(d)), "l"(s) : "memory")

__device__ __forceinline__ void ldsm4(uint32_t* r, uint32_t addr) {
    asm volatile("ldmatrix.sync.aligned.m8n8.x4.shared.b16 {%0,%1,%2,%3}, [%4];"
        : "=r"(r[0]), "=r"(r[1]), "=r"(r[2]), "=r"(r[3]) : "r"(addr));
}

__device__ __forceinline__ void mma_bf16(float* c, const uint32_t* a, uint32_t b0, uint32_t b1) {
    asm volatile("mma.sync.aligned.m16n8k16.row.col.f32.bf16.bf16.f32 "
        "{%0,%1,%2,%3}, {%4,%5,%6,%7}, {%8,%9}, {%0,%1,%2,%3};"
        : "+f"(c[0]), "+f"(c[1]), "+f"(c[2]), "+f"(c[3])
        : "r"(a[0]), "r"(a[1]), "r"(a[2]), "r"(a[3]), "r"(b0), "r"(b1));
}

__device__ __forceinline__ void mma_f16(float* c, const uint32_t* a, uint32_t b0, uint32_t b1) {
    asm volatile("mma.sync.aligned.m16n8k16.row.col.f32.f16.f16.f32 "
        "{%0,%1,%2,%3}, {%4,%5,%6,%7}, {%8,%9}, {%0,%1,%2,%3};"
        : "+f"(c[0]), "+f"(c[1]), "+f"(c[2]), "+f"(c[3])
        : "r"(a[0]), "r"(a[1]), "r"(a[2]), "r"(a[3]), "r"(b0), "r"(b1));
}

// exp2 without MUFU: magic-number round + deg-5 poly + exponent splice.
__device__ __forceinline__ float exp2p(float y) {
    y = fmaxf(y, -126.0f);
    float t = y + 12582912.0f;
    int   n = __float_as_int(t) - 0x4B400000;
    float f = y - (t - 12582912.0f);
    float p = 0.0013333558f;
    p = fmaf(p, f, 0.0096181291f);
    p = fmaf(p, f, 0.0555041087f);
    p = fmaf(p, f, 0.2402265069f);
    p = fmaf(p, f, 0.6931471806f);
    p = fmaf(p, f, 1.0f);
    return p * __int_as_float((n + 127) << 23);
}

__device__ __forceinline__ uint32_t pack_h2(float a, float b) {
    __half2 h = __floats2half2_rn(a, b);
    return *reinterpret_cast<uint32_t*>(&h);
}

// ---------------- RoPE tables ------------------------------------------------
__global__ void rope_table_kernel() {
    int idx = blockIdx.x * blockDim.x + threadIdx.x;
    if (idx >= CS*32) return;
    int p = idx >> 5;
    int j = idx & 31;
    double expo = (double)(2*j) / 64.0;
    double freq = exp(-expo * log(10000.0));
    double ang  = (double)p * freq;
    g_cos[idx] = (float)cos(ang);
    g_sin[idx] = (float)sin(ang);
}

__global__ void rope_apply_kernel(const int* __restrict__ posids) {
    int idx = blockIdx.x * blockDim.x + threadIdx.x;
    int j  = idx & 31;
    int s  = (idx >> 5) & (CS - 1);
    int bh = idx >> 17;
    int b  = bh >> 4;
    int p  = posids[b*CS + s];
    float c  = g_cos[p*32 + j];
    float sn = g_sin[p*32 + j];
    size_t base = ((size_t)bh*CS + (size_t)s)*CHD + j;
    float q1 = g_q[base], q2 = g_q[base+32];
    g_q16[base]    = __float2half(q1*c - q2*sn);
    g_q16[base+32] = __float2half(q2*c + q1*sn);
    float k1 = g_k[base], k2 = g_k[base+32];
    g_k16[base]    = __float2half(k1*c - k2*sn);
    g_k16[base+32] = __float2half(k2*c + k1*sn);
}

// V: fp32 (bh,s,hd) -> fp16 transposed (bh,hd,s)
__global__ void conv_vt_kernel() {
    __shared__ float t[32][33];
    int bh = blockIdx.z;
    int s0 = blockIdx.x * 32;
    int h0 = blockIdx.y * 32;
    int tx = threadIdx.x, ty = threadIdx.y;   // 32 x 8
#pragma unroll
    for (int r = 0; r < 4; r++)
        t[ty + 8*r][tx] = g_v[((size_t)bh*CS + s0 + ty + 8*r)*CHD + h0 + tx];
    __syncthreads();
#pragma unroll
    for (int r = 0; r < 4; r++)
        g_vt[((size_t)bh*CHD + h0 + ty + 8*r)*CS + s0 + tx] = __float2half(t[tx][ty + 8*r]);
}

// ---------------- fp32 -> bf16 hi/lo split (row-major A) ---------------------
__global__ void conv_split_kernel(const float* __restrict__ src, int use_attn) {
    const float* p = use_attn ? (const float*)g_attn : src;
    int i = blockIdx.x * blockDim.x + threadIdx.x;
    size_t base = (size_t)i * 4;
    float4 v = *(const float4*)(p + base);
    __nv_bfloat16 h0 = __float2bfloat16(v.x);
    __nv_bfloat16 h1 = __float2bfloat16(v.y);
    __nv_bfloat16 h2 = __float2bfloat16(v.z);
    __nv_bfloat16 h3 = __float2bfloat16(v.w);
    __nv_bfloat16 l0 = __float2bfloat16(v.x - __bfloat162float(h0));
    __nv_bfloat16 l1 = __float2bfloat16(v.y - __bfloat162float(h1));
    __nv_bfloat16 l2 = __float2bfloat16(v.z - __bfloat162float(h2));
    __nv_bfloat16 l3 = __float2bfloat16(v.w - __bfloat162float(h3));
    *(__nv_bfloat162*)(g_Ah + base)     = __nv_bfloat162(h0, h1);
    *(__nv_bfloat162*)(g_Ah + base + 2) = __nv_bfloat162(h2, h3);
    *(__nv_bfloat162*)(g_Al + base)     = __nv_bfloat162(l0, l1);
    *(__nv_bfloat162*)(g_Al + base + 2) = __nv_bfloat162(l2, l3);
}

// ---------------- weights: fp32 [k][n] -> bf16 hi/lo transposed [n][k] -------
__global__ void conv_w_kernel(const float* __restrict__ w0, const float* __restrict__ w1,
                              const float* __restrict__ w2, const float* __restrict__ w3) {
    __shared__ float t[32][33];
    int wz = blockIdx.z;
    const float* W = (wz == 0) ? w0 : (wz == 1) ? w1 : (wz == 2) ? w2 : w3;
    int n0 = blockIdx.x * 32, k0 = blockIdx.y * 32;
    int tx = threadIdx.x, ty = threadIdx.y;   // 32 x 8
#pragma unroll
    for (int r = 0; r < 4; r++) {
        int k = ty + r*8;
        t[k][tx] = W[(size_t)(k0 + k)*CD + n0 + tx];
    }
    __syncthreads();
    size_t off = (size_t)wz * CD * CD;
#pragma unroll
    for (int r = 0; r < 4; r++) {
        int nn = ty + r*8;
        float x = t[tx][nn];
        __nv_bfloat16 h = __float2bfloat16(x);
        __nv_bfloat16 l = __float2bfloat16(x - __bfloat162float(h));
        g_Wh[off + (size_t)(n0 + nn)*CD + k0 + tx] = h;
        g_Wl[off + (size_t)(n0 + nn)*CD + k0 + tx] = l;
    }
}

// ---------------- split-bf16 GEMM via mma.sync (m16n8k16) --------------------
// 512 threads, 16 warps (4m x 4n), warp tile 32x32 -> 4 warps/SMSP.
// fused=1: QKV fused launch, grid (64, 24): widx = by>>3, n0 = (by&7)*128
// fused=0: output proj,    grid (64, 8):  widx = 3,     n0 = by*128
#define G_TILE    16384
#define G_STAGE   (4*G_TILE)
#define G_SMEM    (1024 + 2*G_STAGE)

__device__ __forceinline__ void g_load_stage(uint32_t dat, int s, int m0, int n0, int tid,
                                             const __nv_bfloat16* Bh, const __nv_bfloat16* Bl) {
    uint32_t buf = dat + (uint32_t)(s & 1) * G_STAGE;
    int k0 = s * 64;
#pragma unroll
    for (int i = 0; i < 2; i++) {
        int cc  = tid + 512*i;
        int row = cc >> 3;
        int kc  = cc & 7;
        uint32_t d = SWZ(row*128 + kc*16);
        size_t ea = (size_t)(m0 + row)*CD + k0 + kc*8;
        size_t eb = (size_t)(n0 + row)*CD + k0 + kc*8;
        CP16(buf + d,             g_Ah + ea);
        CP16(buf + G_TILE + d,    g_Al + ea);
        CP16(buf + 2*G_TILE + d,  Bh + eb);
        CP16(buf + 3*G_TILE + d,  Bl + eb);
    }
    asm volatile("cp.async.commit_group;" ::: "memory");
}

__global__ __launch_bounds__(512) void gemm_tc(int fused, float* __restrict__ outp) {
    extern __shared__ char smem_raw[];
    uint32_t sb_raw = smem_u32(smem_raw);
    uint32_t dat = (sb_raw + 1023u) & ~1023u;

    const int tid  = threadIdx.x;
    const int wid  = tid >> 5, lane = tid & 31;
    const int wm   = wid >> 2;          // 0..3 -> m rows wm*32
    const int wn   = wid & 3;           // 0..3 -> n cols wn*32
    const int m0   = blockIdx.x * 128;
    const int widx = fused ? (int)(blockIdx.y >> 3) : 3;
    const int n0   = fused ? (int)(blockIdx.y & 7) * 128 : (int)blockIdx.y * 128;
    const int mode = fused ? widx : 3;

    const __nv_bfloat16* Bh = g_Wh + ((size_t)widx << 20);
    const __nv_bfloat16* Bl = g_Wl + ((size_t)widx << 20);

    float acc[2][4][4];
#pragma unroll
    for (int mt = 0; mt < 2; mt++)
#pragma unroll
        for (int nt = 0; nt < 4; nt++)
#pragma unroll
            for (int e = 0; e < 4; e++) acc[mt][nt][e] = 0.f;

    const int g  = lane >> 3, r = lane & 7;
    const int arow = wm*32 + (g & 1)*8 + r;          // + mt*16
    const int brow = wn*32 + (g & 1)*8 + r;          // + ng*16
    const int kcol = (g >> 1) * 16;

    g_load_stage(dat, 0, m0, n0, tid, Bh, Bl);

    for (int s = 0; s < 16; s++) {
        if (s + 1 < 16) {
            g_load_stage(dat, s + 1, m0, n0, tid, Bh, Bl);
            asm volatile("cp.async.wait_group 1;" ::: "memory");
        } else {
            asm volatile("cp.async.wait_group 0;" ::: "memory");
        }
        __syncthreads();

        uint32_t buf = dat + (uint32_t)(s & 1) * G_STAGE;
        uint32_t tAh = buf, tAl = buf + G_TILE, tBh = buf + 2*G_TILE, tBl = buf + 3*G_TILE;

#pragma unroll
        for (int ks = 0; ks < 4; ks++) {
            const int kb = ks*32 + kcol;
            uint32_t ah[2][4], al[2][4], bh[2][4], bl[2][4];
#pragma unroll
            for (int mt = 0; mt < 2; mt++) {
                ldsm4(ah[mt], tAh + SWZ((arow + mt*16)*128 + kb));
                ldsm4(al[mt], tAl + SWZ((arow + mt*16)*128 + kb));
            }
#pragma unroll
            for (int ng = 0; ng < 2; ng++) {
                ldsm4(bh[ng], tBh + SWZ((brow + ng*16)*128 + kb));
                ldsm4(bl[ng], tBl + SWZ((brow + ng*16)*128 + kb));
            }
#pragma unroll
            for (int mt = 0; mt < 2; mt++)
#pragma unroll
                for (int nt = 0; nt < 4; nt++) {
                    int ng = nt >> 1, j = nt & 1;
                    mma_bf16(acc[mt][nt], ah[mt], bh[ng][j], bh[ng][j+2]);
                    mma_bf16(acc[mt][nt], ah[mt], bl[ng][j], bl[ng][j+2]);
                    mma_bf16(acc[mt][nt], al[mt], bh[ng][j], bh[ng][j+2]);
                }
        }
        __syncthreads();
    }

    // epilogue
    const int gid = lane >> 2, tig = lane & 3;
    const int b_ = m0 >> 12;
    float* dst = (mode == 0) ? g_q : (mode == 1) ? g_k : g_v;
#pragma unroll
    for (int mt = 0; mt < 2; mt++) {
#pragma unroll
        for (int nt = 0; nt < 4; nt++) {
            int mrow = m0 + wm*32 + mt*16 + gid;
            int ncol = n0 + wn*32 + nt*8 + tig*2;
#pragma unroll
            for (int half = 0; half < 2; half++) {
                int m = mrow + half*8;
                float2 val = make_float2(acc[mt][nt][half*2], acc[mt][nt][half*2 + 1]);
                if (mode == 3) {
                    *(float2*)(outp + (size_t)m*CD + ncol) = val;
                } else {
                    int h  = ncol >> 6, hd = ncol & 63;
                    int s_ = m & (CS - 1);
                    *(float2*)(dst + (((size_t)(b_*CH + h))*CS + s_)*CHD + hd) = val;
                }
            }
        }
    }
}

// ---------------- fp16 tensor-core flash attention ---------------------------
#define AT_TILE   8192
#define AT_SMEM   (1024 + 5*AT_TILE)

__device__ __forceinline__ void at_stage(uint32_t kbuf, const __half* ksrc,
                                         const __half* vtsrc, int tid) {
#pragma unroll
    for (int i = 0; i < 4; i++) {
        int cc  = tid + 128*i;
        int row = cc >> 3;
        int kc  = cc & 7;
        uint32_t d = SWZ(row*128 + kc*16);
        CP16(kbuf + d,           ksrc  + (size_t)row*CHD + kc*8);
        CP16(kbuf + AT_TILE + d, vtsrc + (size_t)row*CS  + kc*8);
    }
    asm volatile("cp.async.commit_group;" ::: "memory");
}

__global__ __launch_bounds__(128) void attn_tc_kernel() {
    extern __shared__ char sraw[];
    uint32_t dat = (smem_u32(sraw) + 1023u) & ~1023u;

    const int n   = blockIdx.x;
    const int bh  = blockIdx.y;
    const int tid = threadIdx.x;
    const int w   = tid >> 5, lane = tid & 31;
    const int g   = lane >> 3, r = lane & 7;
    const int gid = lane >> 2, tig = lane & 3;

    const __half* qsrc = g_q16 + ((size_t)bh*CS + (size_t)n*64)*CHD;
#pragma unroll
    for (int i = 0; i < 4; i++) {
        int cc = tid + 128*i;
        int row = cc >> 3;
        int kc  = cc & 7;
        CP16(dat + SWZ(row*128 + kc*16), qsrc + (size_t)row*CHD + kc*8);
    }
    asm volatile("cp.async.commit_group;" ::: "memory");

    const int kb0 = (n - (CW-1) < 0) ? 0 : n - (CW-1);
    const int nk  = n - kb0 + 1;
    const __half* kbase_g  = g_k16 + ((size_t)bh*CS)*CHD;
    const __half* vtbase_g = g_vt  + ((size_t)bh*CHD)*CS;

    at_stage(dat + AT_TILE, kbase_g + (size_t)kb0*64*CHD, vtbase_g + kb0*64, tid);

    float oacc[8][4];
#pragma unroll
    for (int nt = 0; nt < 8; nt++)
#pragma unroll
        for (int e = 0; e < 4; e++) oacc[nt][e] = 0.f;
    float m0 = -1e30f, m1 = -1e30f, l0 = 0.f, l1 = 0.f;
    uint32_t qf[4][4];

    const float SCL = 0.18033688011f;    // 0.125 * log2(e)
    const int ql0 = w*16 + gid, ql1 = ql0 + 8;

    for (int i = 0; i < nk; i++) {
        const int kb = kb0 + i;
        asm volatile("cp.async.wait_group 0;" ::: "memory");
        __syncthreads();

        if (i == 0) {
#pragma unroll
            for (int kc = 0; kc < 4; kc++)
                ldsm4(qf[kc], dat + SWZ((w*16 + (g&1)*8 + r)*128 + (g>>1)*16 + kc*32));
        }
        if (i + 1 < nk)
            at_stage(dat + AT_TILE + ((i+1)&1)*2*AT_TILE,
                     kbase_g + (size_t)(kb+1)*64*CHD, vtbase_g + (kb+1)*64, tid);

        const uint32_t kbuf = dat + AT_TILE + (i&1)*2*AT_TILE;
        const uint32_t vbuf = kbuf + AT_TILE;

        float sacc[8][4];
#pragma unroll
        for (int nt = 0; nt < 8; nt++)
#pragma unroll
            for (int e = 0; e < 4; e++) sacc[nt][e] = 0.f;

#pragma unroll
        for (int kc = 0; kc < 4; kc++) {
            uint32_t kf[4][4];
#pragma unroll
            for (int ng = 0; ng < 4; ng++)
                ldsm4(kf[ng], kbuf + SWZ((ng*16 + (g&1)*8 + r)*128 + (g>>1)*16 + kc*32));
#pragma unroll
            for (int nt = 0; nt < 8; nt++)
                mma_f16(sacc[nt], qf[kc], kf[nt>>1][nt&1], kf[nt>>1][(nt&1)+2]);
        }

#pragma unroll
        for (int nt = 0; nt < 8; nt++)
#pragma unroll
            for (int e = 0; e < 4; e++) sacc[nt][e] *= SCL;
        if (kb == n) {
#pragma unroll
            for (int nt = 0; nt < 8; nt++) {
                int c0 = nt*8 + 2*tig, c1 = c0 + 1;
                if (c0 > ql0) sacc[nt][0] = -1e30f;
                if (c1 > ql0) sacc[nt][1] = -1e30f;
                if (c0 > ql1) sacc[nt][2] = -1e30f;
                if (c1 > ql1) sacc[nt][3] = -1e30f;
            }
        }

        float mx0 = -1e30f, mx1 = -1e30f;
#pragma unroll
        for (int nt = 0; nt < 8; nt++) {
            mx0 = fmaxf(mx0, fmaxf(sacc[nt][0], sacc[nt][1]));
            mx1 = fmaxf(mx1, fmaxf(sacc[nt][2], sacc[nt][3]));
        }
        mx0 = fmaxf(mx0, __shfl_xor_sync(0xffffffffu, mx0, 1));
        mx0 = fmaxf(mx0, __shfl_xor_sync(0xffffffffu, mx0, 2));
        mx1 = fmaxf(mx1, __shfl_xor_sync(0xffffffffu, mx1, 1));
        mx1 = fmaxf(mx1, __shfl_xor_sync(0xffffffffu, mx1, 2));
        float mn0 = fmaxf(m0, mx0), mn1 = fmaxf(m1, mx1);
        float cr0 = exp2p(m0 - mn0), cr1 = exp2p(m1 - mn1);
        m0 = mn0; m1 = mn1;
        float rs0 = 0.f, rs1 = 0.f;
#pragma unroll
        for (int nt = 0; nt < 8; nt++) {
            sacc[nt][0] = exp2p(sacc[nt][0] - mn0);
            sacc[nt][1] = exp2p(sacc[nt][1] - mn0);
            sacc[nt][2] = exp2p(sacc[nt][2] - mn1);
            sacc[nt][3] = exp2p(sacc[nt][3] - mn1);
            rs0 += sacc[nt][0] + sacc[nt][1];
            rs1 += sacc[nt][2] + sacc[nt][3];
        }
        rs0 += __shfl_xor_sync(0xffffffffu, rs0, 1);
        rs0 += __shfl_xor_sync(0xffffffffu, rs0, 2);
        rs1 += __shfl_xor_sync(0xffffffffu, rs1, 1);
        rs1 += __shfl_xor_sync(0xffffffffu, rs1, 2);
        l0 = l0*cr0 + rs0;
        l1 = l1*cr1 + rs1;
#pragma unroll
        for (int nt = 0; nt < 8; nt++) {
            oacc[nt][0] *= cr0; oacc[nt][1] *= cr0;
            oacc[nt][2] *= cr1; oacc[nt][3] *= cr1;
        }

#pragma unroll
        for (int kc = 0; kc < 4; kc++) {
            uint32_t pf[4];
            pf[0] = pack_h2(sacc[2*kc][0],   sacc[2*kc][1]);
            pf[1] = pack_h2(sacc[2*kc][2],   sacc[2*kc][3]);
            pf[2] = pack_h2(sacc[2*kc+1][0], sacc[2*kc+1][1]);
            pf[3] = pack_h2(sacc[2*kc+1][2], sacc[2*kc+1][3]);
            uint32_t vf[4][4];
#pragma unroll
            for (int ng = 0; ng < 4; ng++)
                ldsm4(vf[ng], vbuf + SWZ((ng*16 + (g&1)*8 + r)*128 + (g>>1)*16 + kc*32));
#pragma unroll
            for (int nt = 0; nt < 8; nt++)
                mma_f16(oacc[nt], pf, vf[nt>>1][nt&1], vf[nt>>1][(nt&1)+2]);
        }
        __syncthreads();
    }

    const float inv0 = 1.0f / l0, inv1 = 1.0f / l1;
    const int b = bh >> 4, h = bh & 15;
    const int srow = n*64 + w*16 + gid;
#pragma unroll
    for (int nt = 0; nt < 8; nt++) {
        int col = h*CHD + nt*8 + 2*tig;
        *(float2*)(g_attn + ((size_t)b*CS + srow)*CD + col) =
            make_float2(oacc[nt][0]*inv0, oacc[nt][1]*inv0);
        *(float2*)(g_attn + ((size_t)b*CS + srow + 8)*CD + col) =
            make_float2(oacc[nt][2]*inv1, oacc[nt][3]*inv1);
    }
}

// ---------------- launch -----------------------------------------------------
extern "C" void kernel_launch(void* const* d_in, const int* in_sizes, int n_in,
                              void* d_out, int out_size) {
    const float* hidden = (const float*)d_in[0];
    const int*   posids = (const int*)d_in[1];
    const float* wq = (const float*)d_in[2];
    const float* wk = (const float*)d_in[3];
    const float* wv = (const float*)d_in[4];
    const float* wo = (const float*)d_in[5];
    float* out = (float*)d_out;

    cudaFuncSetAttribute(gemm_tc, cudaFuncAttributeMaxDynamicSharedMemorySize, G_SMEM);
    cudaFuncSetAttribute(attn_tc_kernel, cudaFuncAttributeMaxDynamicSharedMemorySize, AT_SMEM);

    conv_w_kernel<<<dim3(32, 32, 4), dim3(32, 8)>>>(wq, wk, wv, wo);
    conv_split_kernel<<<(CM*CD/4)/256, 256>>>(hidden, 0);
    rope_table_kernel<<<(CS*32 + 255)/256, 256>>>();

    // fused QKV: grid (64, 24)
    gemm_tc<<<dim3(CM/128, 24), 512, G_SMEM>>>(1, nullptr);

    rope_apply_kernel<<<(CB*CH*CS*32)/256, 256>>>(posids);
    conv_vt_kernel<<<dim3(CS/32, CHD/32, CB*CH), dim3(32, 8)>>>();

    attn_tc_kernel<<<dim3(CNB, CB*CH), 128, AT_SMEM>>>();

    conv_split_kernel<<<(CM*CD/4)/256, 256>>>(nullptr, 1);
    gemm_tc<<<dim3(CM/128, CD/128), 512, G_SMEM>>>(0, out);
}

// round 13
// speedup vs baseline: 3.1938x; 1.0189x over previous
#include <cuda_runtime.h>
#include <cuda_bf16.h>
#include <cuda_fp16.h>
#include <cstdint>
#include <math.h>

#define CB   2
#define CS   4096
#define CD   1024
#define CH   16
#define CHD  64
#define CNB  64
#define CW   8
#define CM   (CB*CS)

// ---------------- scratch (device globals) ----------------------------------
__device__ float g_q[(size_t)CB*CH*CS*CHD];
__device__ float g_k[(size_t)CB*CH*CS*CHD];
__device__ float g_v[(size_t)CB*CH*CS*CHD];
__device__ float g_cos[CS*32];
__device__ float g_sin[CS*32];
__device__ __align__(256) __nv_bfloat16 g_Ah[(size_t)CM*CD];
__device__ __align__(256) __nv_bfloat16 g_Al[(size_t)CM*CD];
__device__ __align__(256) __nv_bfloat16 g_Wh[(size_t)4*CD*CD];   // [n][k] transposed
__device__ __align__(256) __nv_bfloat16 g_Wl[(size_t)4*CD*CD];
__device__ __align__(256) __half g_q16[(size_t)CB*CH*CS*CHD];    // (bh,s,hd)
__device__ __align__(256) __half g_k16[(size_t)CB*CH*CS*CHD];    // (bh,s,hd)
__device__ __align__(256) __half g_vt [(size_t)CB*CH*CHD*CS];    // (bh,hd,s)

// ---------------- helpers ----------------------------------------------------
__device__ __forceinline__ uint32_t smem_u32(const void* p) {
    uint32_t a;
    asm("{ .reg .u64 t; cvta.to.shared.u64 t, %1; cvt.u32.u64 %0, t; }" : "=r"(a) : "l"(p));
    return a;
}
#define SWZ(o) ((o) ^ (((o) >> 3) & 0x70))

#define CP16(d, s) \
    asm volatile("cp.async.cg.shared.global [%0], [%1], 16;" :: "r"((uint32_t)(d)), "l"(s) : "memory")

__device__ __forceinline__ void ldsm4(uint32_t* r, uint32_t addr) {
    asm volatile("ldmatrix.sync.aligned.m8n8.x4.shared.b16 {%0,%1,%2,%3}, [%4];"
        : "=r"(r[0]), "=r"(r[1]), "=r"(r[2]), "=r"(r[3]) : "r"(addr));
}

__device__ __forceinline__ void mma_bf16(float* c, const uint32_t* a, uint32_t b0, uint32_t b1) {
    asm volatile("mma.sync.aligned.m16n8k16.row.col.f32.bf16.bf16.f32 "
        "{%0,%1,%2,%3}, {%4,%5,%6,%7}, {%8,%9}, {%0,%1,%2,%3};"
        : "+f"(c[0]), "+f"(c[1]), "+f"(c[2]), "+f"(c[3])
        : "r"(a[0]), "r"(a[1]), "r"(a[2]), "r"(a[3]), "r"(b0), "r"(b1));
}

__device__ __forceinline__ void mma_f16(float* c, const uint32_t* a, uint32_t b0, uint32_t b1) {
    asm volatile("mma.sync.aligned.m16n8k16.row.col.f32.f16.f16.f32 "
        "{%0,%1,%2,%3}, {%4,%5,%6,%7}, {%8,%9}, {%0,%1,%2,%3};"
        : "+f"(c[0]), "+f"(c[1]), "+f"(c[2]), "+f"(c[3])
        : "r"(a[0]), "r"(a[1]), "r"(a[2]), "r"(a[3]), "r"(b0), "r"(b1));
}

// exp2 without MUFU: magic-number round + deg-5 poly + exponent splice.
__device__ __forceinline__ float exp2p(float y) {
    y = fmaxf(y, -126.0f);
    float t = y + 12582912.0f;
    int   n = __float_as_int(t) - 0x4B400000;
    float f = y - (t - 12582912.0f);
    float p = 0.0013333558f;
    p = fmaf(p, f, 0.0096181291f);
    p = fmaf(p, f, 0.0555041087f);
    p = fmaf(p, f, 0.2402265069f);
    p = fmaf(p, f, 0.6931471806f);
    p = fmaf(p, f, 1.0f);
    return p * __int_as_float((n + 127) << 23);
}

__device__ __forceinline__ uint32_t pack_h2(float a, float b) {
    __half2 h = __floats2half2_rn(a, b);
    return *reinterpret_cast<uint32_t*>(&h);
}

// bf16 hi/lo split of one fp32 (matches conv_split rounding exactly)
__device__ __forceinline__ void split_bf16(float x, __nv_bfloat16& h, __nv_bfloat16& l) {
    h = __float2bfloat16(x);
    l = __float2bfloat16(x - __bfloat162float(h));
}

// ---------------- RoPE tables ------------------------------------------------
__global__ void rope_table_kernel() {
    int idx = blockIdx.x * blockDim.x + threadIdx.x;
    if (idx >= CS*32) return;
    int p = idx >> 5;
    int j = idx & 31;
    double expo = (double)(2*j) / 64.0;
    double freq = exp(-expo * log(10000.0));
    double ang  = (double)p * freq;
    g_cos[idx] = (float)cos(ang);
    g_sin[idx] = (float)sin(ang);
}

__global__ void rope_apply_kernel(const int* __restrict__ posids) {
    int idx = blockIdx.x * blockDim.x + threadIdx.x;
    int j  = idx & 31;
    int s  = (idx >> 5) & (CS - 1);
    int bh = idx >> 17;
    int b  = bh >> 4;
    int p  = posids[b*CS + s];
    float c  = g_cos[p*32 + j];
    float sn = g_sin[p*32 + j];
    size_t base = ((size_t)bh*CS + (size_t)s)*CHD + j;
    float q1 = g_q[base], q2 = g_q[base+32];
    g_q16[base]    = __float2half(q1*c - q2*sn);
    g_q16[base+32] = __float2half(q2*c + q1*sn);
    float k1 = g_k[base], k2 = g_k[base+32];
    g_k16[base]    = __float2half(k1*c - k2*sn);
    g_k16[base+32] = __float2half(k2*c + k1*sn);
}

// V: fp32 (bh,s,hd) -> fp16 transposed (bh,hd,s)
__global__ void conv_vt_kernel() {
    __shared__ float t[32][33];
    int bh = blockIdx.z;
    int s0 = blockIdx.x * 32;
    int h0 = blockIdx.y * 32;
    int tx = threadIdx.x, ty = threadIdx.y;   // 32 x 8
#pragma unroll
    for (int r = 0; r < 4; r++)
        t[ty + 8*r][tx] = g_v[((size_t)bh*CS + s0 + ty + 8*r)*CHD + h0 + tx];
    __syncthreads();
#pragma unroll
    for (int r = 0; r < 4; r++)
        g_vt[((size_t)bh*CHD + h0 + ty + 8*r)*CS + s0 + tx] = __float2half(t[tx][ty + 8*r]);
}

// ---------------- fp32 -> bf16 hi/lo split (row-major A) ---------------------
__global__ void conv_split_kernel(const float* __restrict__ src) {
    int i = blockIdx.x * blockDim.x + threadIdx.x;
    size_t base = (size_t)i * 4;
    float4 v = *(const float4*)(src + base);
    __nv_bfloat16 h0, h1, h2, h3, l0, l1, l2, l3;
    split_bf16(v.x, h0, l0);
    split_bf16(v.y, h1, l1);
    split_bf16(v.z, h2, l2);
    split_bf16(v.w, h3, l3);
    *(__nv_bfloat162*)(g_Ah + base)     = __nv_bfloat162(h0, h1);
    *(__nv_bfloat162*)(g_Ah + base + 2) = __nv_bfloat162(h2, h3);
    *(__nv_bfloat162*)(g_Al + base)     = __nv_bfloat162(l0, l1);
    *(__nv_bfloat162*)(g_Al + base + 2) = __nv_bfloat162(l2, l3);
}

// ---------------- weights: fp32 [k][n] -> bf16 hi/lo transposed [n][k] -------
__global__ void conv_w_kernel(const float* __restrict__ w0, const float* __restrict__ w1,
                              const float* __restrict__ w2, const float* __restrict__ w3) {
    __shared__ float t[32][33];
    int wz = blockIdx.z;
    const float* W = (wz == 0) ? w0 : (wz == 1) ? w1 : (wz == 2) ? w2 : w3;
    int n0 = blockIdx.x * 32, k0 = blockIdx.y * 32;
    int tx = threadIdx.x, ty = threadIdx.y;   // 32 x 8
#pragma unroll
    for (int r = 0; r < 4; r++) {
        int k = ty + r*8;
        t[k][tx] = W[(size_t)(k0 + k)*CD + n0 + tx];
    }
    __syncthreads();
    size_t off = (size_t)wz * CD * CD;
#pragma unroll
    for (int r = 0; r < 4; r++) {
        int nn = ty + r*8;
        float x = t[tx][nn];
        __nv_bfloat16 h, l;
        split_bf16(x, h, l);
        g_Wh[off + (size_t)(n0 + nn)*CD + k0 + tx] = h;
        g_Wl[off + (size_t)(n0 + nn)*CD + k0 + tx] = l;
    }
}

// ---------------- split-bf16 GEMM via mma.sync (m16n8k16) --------------------
// 512 threads, 16 warps (4m x 4n), warp tile 32x32.
// Product-major MMA ordering + ldsm double-buffer across k-steps.
#define G_TILE    16384
#define G_STAGE   (4*G_TILE)
#define G_SMEM    (1024 + 2*G_STAGE)

__device__ __forceinline__ void g_load_stage(uint32_t dat, int s, int m0, int n0, int tid,
                                             const __nv_bfloat16* Bh, const __nv_bfloat16* Bl) {
    uint32_t buf = dat + (uint32_t)(s & 1) * G_STAGE;
    int k0 = s * 64;
#pragma unroll
    for (int i = 0; i < 2; i++) {
        int cc  = tid + 512*i;
        int row = cc >> 3;
        int kc  = cc & 7;
        uint32_t d = SWZ(row*128 + kc*16);
        size_t ea = (size_t)(m0 + row)*CD + k0 + kc*8;
        size_t eb = (size_t)(n0 + row)*CD + k0 + kc*8;
        CP16(buf + d,             g_Ah + ea);
        CP16(buf + G_TILE + d,    g_Al + ea);
        CP16(buf + 2*G_TILE + d,  Bh + eb);
        CP16(buf + 3*G_TILE + d,  Bl + eb);
    }
    asm volatile("cp.async.commit_group;" ::: "memory");
}

__global__ __launch_bounds__(512) void gemm_tc(int fused, float* __restrict__ outp) {
    extern __shared__ char smem_raw[];
    uint32_t sb_raw = smem_u32(smem_raw);
    uint32_t dat = (sb_raw + 1023u) & ~1023u;

    const int tid  = threadIdx.x;
    const int wid  = tid >> 5, lane = tid & 31;
    const int wm   = wid >> 2;
    const int wn   = wid & 3;
    const int m0   = blockIdx.x * 128;
    const int widx = fused ? (int)(blockIdx.y >> 3) : 3;
    const int n0   = fused ? (int)(blockIdx.y & 7) * 128 : (int)blockIdx.y * 128;
    const int mode = fused ? widx : 3;

    const __nv_bfloat16* Bh = g_Wh + ((size_t)widx << 20);
    const __nv_bfloat16* Bl = g_Wl + ((size_t)widx << 20);

    float acc[2][4][4];
#pragma unroll
    for (int mt = 0; mt < 2; mt++)
#pragma unroll
        for (int nt = 0; nt < 4; nt++)
#pragma unroll
            for (int e = 0; e < 4; e++) acc[mt][nt][e] = 0.f;

    const int g  = lane >> 3, r = lane & 7;
    const int arow = wm*32 + (g & 1)*8 + r;
    const int brow = wn*32 + (g & 1)*8 + r;
    const int kcol = (g >> 1) * 16;

    // operand double-buffer across k-steps
    uint32_t ah[2][2][4], al[2][2][4], bhx[2][2][4], blx[2][2][4];

    g_load_stage(dat, 0, m0, n0, tid, Bh, Bl);

    for (int s = 0; s < 16; s++) {
        if (s + 1 < 16) {
            g_load_stage(dat, s + 1, m0, n0, tid, Bh, Bl);
            asm volatile("cp.async.wait_group 1;" ::: "memory");
        } else {
            asm volatile("cp.async.wait_group 0;" ::: "memory");
        }
        __syncthreads();

        uint32_t buf = dat + (uint32_t)(s & 1) * G_STAGE;
        uint32_t tAh = buf, tAl = buf + G_TILE, tBh = buf + 2*G_TILE, tBl = buf + 3*G_TILE;

        // prime k-step 0
#pragma unroll
        for (int mt = 0; mt < 2; mt++) {
            ldsm4(ah[0][mt], tAh + SWZ((arow + mt*16)*128 + kcol));
            ldsm4(al[0][mt], tAl + SWZ((arow + mt*16)*128 + kcol));
        }
#pragma unroll
        for (int ng = 0; ng < 2; ng++) {
            ldsm4(bhx[0][ng], tBh + SWZ((brow + ng*16)*128 + kcol));
            ldsm4(blx[0][ng], tBl + SWZ((brow + ng*16)*128 + kcol));
        }

#pragma unroll
        for (int ks = 0; ks < 4; ks++) {
            const int cur = ks & 1, nxt = cur ^ 1;
            if (ks < 3) {
                const int kb = (ks+1)*32 + kcol;
#pragma unroll
                for (int mt = 0; mt < 2; mt++) {
                    ldsm4(ah[nxt][mt], tAh + SWZ((arow + mt*16)*128 + kb));
                    ldsm4(al[nxt][mt], tAl + SWZ((arow + mt*16)*128 + kb));
                }
#pragma unroll
                for (int ng = 0; ng < 2; ng++) {
                    ldsm4(bhx[nxt][ng], tBh + SWZ((brow + ng*16)*128 + kb));
                    ldsm4(blx[nxt][ng], tBl + SWZ((brow + ng*16)*128 + kb));
                }
            }
            // product-major: 8 independent accumulators between reuses
#pragma unroll
            for (int mt = 0; mt < 2; mt++)
#pragma unroll
                for (int nt = 0; nt < 4; nt++)
                    mma_bf16(acc[mt][nt], ah[cur][mt], bhx[cur][nt>>1][nt&1], bhx[cur][nt>>1][(nt&1)+2]);
#pragma unroll
            for (int mt = 0; mt < 2; mt++)
#pragma unroll
                for (int nt = 0; nt < 4; nt++)
                    mma_bf16(acc[mt][nt], ah[cur][mt], blx[cur][nt>>1][nt&1], blx[cur][nt>>1][(nt&1)+2]);
#pragma unroll
            for (int mt = 0; mt < 2; mt++)
#pragma unroll
                for (int nt = 0; nt < 4; nt++)
                    mma_bf16(acc[mt][nt], al[cur][mt], bhx[cur][nt>>1][nt&1], bhx[cur][nt>>1][(nt&1)+2]);
        }
        __syncthreads();
    }

    // epilogue
    const int gid = lane >> 2, tig = lane & 3;
    const int b_ = m0 >> 12;
    float* dst = (mode == 0) ? g_q : (mode == 1) ? g_k : g_v;
#pragma unroll
    for (int mt = 0; mt < 2; mt++) {
#pragma unroll
        for (int nt = 0; nt < 4; nt++) {
            int mrow = m0 + wm*32 + mt*16 + gid;
            int ncol = n0 + wn*32 + nt*8 + tig*2;
#pragma unroll
            for (int half = 0; half < 2; half++) {
                int m = mrow + half*8;
                float2 val = make_float2(acc[mt][nt][half*2], acc[mt][nt][half*2 + 1]);
                if (mode == 3) {
                    *(float2*)(outp + (size_t)m*CD + ncol) = val;
                } else {
                    int h  = ncol >> 6, hd = ncol & 63;
                    int s_ = m & (CS - 1);
                    *(float2*)(dst + (((size_t)(b_*CH + h))*CS + s_)*CHD + hd) = val;
                }
            }
        }
    }
}

// ---------------- fp16 tensor-core flash attention ---------------------------
// epilogue writes bf16 hi/lo A-operand for the output projection directly.
#define AT_TILE   8192
#define AT_SMEM   (1024 + 5*AT_TILE)

__device__ __forceinline__ void at_stage(uint32_t kbuf, const __half* ksrc,
                                         const __half* vtsrc, int tid) {
#pragma unroll
    for (int i = 0; i < 4; i++) {
        int cc  = tid + 128*i;
        int row = cc >> 3;
        int kc  = cc & 7;
        uint32_t d = SWZ(row*128 + kc*16);
        CP16(kbuf + d,           ksrc  + (size_t)row*CHD + kc*8);
        CP16(kbuf + AT_TILE + d, vtsrc + (size_t)row*CS  + kc*8);
    }
    asm volatile("cp.async.commit_group;" ::: "memory");
}

__global__ __launch_bounds__(128) void attn_tc_kernel() {
    extern __shared__ char sraw[];
    uint32_t dat = (smem_u32(sraw) + 1023u) & ~1023u;

    const int n   = blockIdx.x;
    const int bh  = blockIdx.y;
    const int tid = threadIdx.x;
    const int w   = tid >> 5, lane = tid & 31;
    const int g   = lane >> 3, r = lane & 7;
    const int gid = lane >> 2, tig = lane & 3;

    const __half* qsrc = g_q16 + ((size_t)bh*CS + (size_t)n*64)*CHD;
#pragma unroll
    for (int i = 0; i < 4; i++) {
        int cc = tid + 128*i;
        int row = cc >> 3;
        int kc  = cc & 7;
        CP16(dat + SWZ(row*128 + kc*16), qsrc + (size_t)row*CHD + kc*8);
    }
    asm volatile("cp.async.commit_group;" ::: "memory");

    const int kb0 = (n - (CW-1) < 0) ? 0 : n - (CW-1);
    const int nk  = n - kb0 + 1;
    const __half* kbase_g  = g_k16 + ((size_t)bh*CS)*CHD;
    const __half* vtbase_g = g_vt  + ((size_t)bh*CHD)*CS;

    at_stage(dat + AT_TILE, kbase_g + (size_t)kb0*64*CHD, vtbase_g + kb0*64, tid);

    float oacc[8][4];
#pragma unroll
    for (int nt = 0; nt < 8; nt++)
#pragma unroll
        for (int e = 0; e < 4; e++) oacc[nt][e] = 0.f;
    float m0 = -1e30f, m1 = -1e30f, l0 = 0.f, l1 = 0.f;
    uint32_t qf[4][4];

    const float SCL = 0.18033688011f;    // 0.125 * log2(e)
    const int ql0 = w*16 + gid, ql1 = ql0 + 8;

    for (int i = 0; i < nk; i++) {
        const int kb = kb0 + i;
        asm volatile("cp.async.wait_group 0;" ::: "memory");
        __syncthreads();

        if (i == 0) {
#pragma unroll
            for (int kc = 0; kc < 4; kc++)
                ldsm4(qf[kc], dat + SWZ((w*16 + (g&1)*8 + r)*128 + (g>>1)*16 + kc*32));
        }
        if (i + 1 < nk)
            at_stage(dat + AT_TILE + ((i+1)&1)*2*AT_TILE,
                     kbase_g + (size_t)(kb+1)*64*CHD, vtbase_g + (kb+1)*64, tid);

        const uint32_t kbuf = dat + AT_TILE + (i&1)*2*AT_TILE;
        const uint32_t vbuf = kbuf + AT_TILE;

        float sacc[8][4];
#pragma unroll
        for (int nt = 0; nt < 8; nt++)
#pragma unroll
            for (int e = 0; e < 4; e++) sacc[nt][e] = 0.f;

#pragma unroll
        for (int kc = 0; kc < 4; kc++) {
            uint32_t kf[4][4];
#pragma unroll
            for (int ng = 0; ng < 4; ng++)
                ldsm4(kf[ng], kbuf + SWZ((ng*16 + (g&1)*8 + r)*128 + (g>>1)*16 + kc*32));
#pragma unroll
            for (int nt = 0; nt < 8; nt++)
                mma_f16(sacc[nt], qf[kc], kf[nt>>1][nt&1], kf[nt>>1][(nt&1)+2]);
        }

#pragma unroll
        for (int nt = 0; nt < 8; nt++)
#pragma unroll
            for (int e = 0; e < 4; e++) sacc[nt][e] *= SCL;
        if (kb == n) {
#pragma unroll
            for (int nt = 0; nt < 8; nt++) {
                int c0 = nt*8 + 2*tig, c1 = c0 + 1;
                if (c0 > ql0) sacc[nt][0] = -1e30f;
                if (c1 > ql0) sacc[nt][1] = -1e30f;
                if (c0 > ql1) sacc[nt][2] = -1e30f;
                if (c1 > ql1) sacc[nt][3] = -1e30f;
            }
        }

        float mx0 = -1e30f, mx1 = -1e30f;
#pragma unroll
        for (int nt = 0; nt < 8; nt++) {
            mx0 = fmaxf(mx0, fmaxf(sacc[nt][0], sacc[nt][1]));
            mx1 = fmaxf(mx1, fmaxf(sacc[nt][2], sacc[nt][3]));
        }
        mx0 = fmaxf(mx0, __shfl_xor_sync(0xffffffffu, mx0, 1));
        mx0 = fmaxf(mx0, __shfl_xor_sync(0xffffffffu, mx0, 2));
        mx1 = fmaxf(mx1, __shfl_xor_sync(0xffffffffu, mx1, 1));
        mx1 = fmaxf(mx1, __shfl_xor_sync(0xffffffffu, mx1, 2));
        float mn0 = fmaxf(m0, mx0), mn1 = fmaxf(m1, mx1);
        float cr0 = exp2p(m0 - mn0), cr1 = exp2p(m1 - mn1);
        m0 = mn0; m1 = mn1;
        float rs0 = 0.f, rs1 = 0.f;
#pragma unroll
        for (int nt = 0; nt < 8; nt++) {
            sacc[nt][0] = exp2p(sacc[nt][0] - mn0);
            sacc[nt][1] = exp2p(sacc[nt][1] - mn0);
            sacc[nt][2] = exp2p(sacc[nt][2] - mn1);
            sacc[nt][3] = exp2p(sacc[nt][3] - mn1);
            rs0 += sacc[nt][0] + sacc[nt][1];
            rs1 += sacc[nt][2] + sacc[nt][3];
        }
        rs0 += __shfl_xor_sync(0xffffffffu, rs0, 1);
        rs0 += __shfl_xor_sync(0xffffffffu, rs0, 2);
        rs1 += __shfl_xor_sync(0xffffffffu, rs1, 1);
        rs1 += __shfl_xor_sync(0xffffffffu, rs1, 2);
        l0 = l0*cr0 + rs0;
        l1 = l1*cr1 + rs1;
#pragma unroll
        for (int nt = 0; nt < 8; nt++) {
            oacc[nt][0] *= cr0; oacc[nt][1] *= cr0;
            oacc[nt][2] *= cr1; oacc[nt][3] *= cr1;
        }

#pragma unroll
        for (int kc = 0; kc < 4; kc++) {
            uint32_t pf[4];
            pf[0] = pack_h2(sacc[2*kc][0],   sacc[2*kc][1]);
            pf[1] = pack_h2(sacc[2*kc][2],   sacc[2*kc][3]);
            pf[2] = pack_h2(sacc[2*kc+1][0], sacc[2*kc+1][1]);
            pf[3] = pack_h2(sacc[2*kc+1][2], sacc[2*kc+1][3]);
            uint32_t vf[4][4];
#pragma unroll
            for (int ng = 0; ng < 4; ng++)
                ldsm4(vf[ng], vbuf + SWZ((ng*16 + (g&1)*8 + r)*128 + (g>>1)*16 + kc*32));
#pragma unroll
            for (int nt = 0; nt < 8; nt++)
                mma_f16(oacc[nt], pf, vf[nt>>1][nt&1], vf[nt>>1][(nt&1)+2]);
        }
        __syncthreads();
    }

    // ---- epilogue: normalize and write bf16 hi/lo directly into g_Ah/g_Al ----
    const float inv0 = 1.0f / l0, inv1 = 1.0f / l1;
    const int b = bh >> 4, h = bh & 15;
    const int srow = n*64 + w*16 + gid;
#pragma unroll
    for (int nt = 0; nt < 8; nt++) {
        int col = h*CHD + nt*8 + 2*tig;
        size_t off0 = ((size_t)b*CS + srow)*CD + col;
        size_t off1 = ((size_t)b*CS + srow + 8)*CD + col;
        __nv_bfloat16 h0, h1, lo0, lo1;
        split_bf16(oacc[nt][0]*inv0, h0, lo0);
        split_bf16(oacc[nt][1]*inv0, h1, lo1);
        *(__nv_bfloat162*)(g_Ah + off0) = __nv_bfloat162(h0, h1);
        *(__nv_bfloat162*)(g_Al + off0) = __nv_bfloat162(lo0, lo1);
        split_bf16(oacc[nt][2]*inv1, h0, lo0);
        split_bf16(oacc[nt][3]*inv1, h1, lo1);
        *(__nv_bfloat162*)(g_Ah + off1) = __nv_bfloat162(h0, h1);
        *(__nv_bfloat162*)(g_Al + off1) = __nv_bfloat162(lo0, lo1);
    }
}

// ---------------- launch -----------------------------------------------------
extern "C" void kernel_launch(void* const* d_in, const int* in_sizes, int n_in,
                              void* d_out, int out_size) {
    const float* hidden = (const float*)d_in[0];
    const int*   posids = (const int*)d_in[1];
    const float* wq = (const float*)d_in[2];
    const float* wk = (const float*)d_in[3];
    const float* wv = (const float*)d_in[4];
    const float* wo = (const float*)d_in[5];
    float* out = (float*)d_out;

    cudaFuncSetAttribute(gemm_tc, cudaFuncAttributeMaxDynamicSharedMemorySize, G_SMEM);
    cudaFuncSetAttribute(attn_tc_kernel, cudaFuncAttributeMaxDynamicSharedMemorySize, AT_SMEM);

    conv_w_kernel<<<dim3(32, 32, 4), dim3(32, 8)>>>(wq, wk, wv, wo);
    conv_split_kernel<<<(CM*CD/4)/256, 256>>>(hidden);
    rope_table_kernel<<<(CS*32 + 255)/256, 256>>>();

    // fused QKV: grid (64, 24)
    gemm_tc<<<dim3(CM/128, 24), 512, G_SMEM>>>(1, nullptr);

    rope_apply_kernel<<<(CB*CH*CS*32)/256, 256>>>(posids);
    conv_vt_kernel<<<dim3(CS/32, CHD/32, CB*CH), dim3(32, 8)>>>();

    // attention writes g_Ah/g_Al (split) directly
    attn_tc_kernel<<<dim3(CNB, CB*CH), 128, AT_SMEM>>>();

    gemm_tc<<<dim3(CM/128, CD/128), 512, G_SMEM>>>(0, out);
}